// round 1
// baseline (speedup 1.0000x reference)
#include <cuda_runtime.h>
#include <math.h>

// Problem constants
#define SEQ 2048
#define DIM 2048
#define NH  16
#define DK  128

// ------------------------------------------------------------------
// Scratch (device globals — no allocations inside kernel_launch)
// ------------------------------------------------------------------
__device__ float g_q[NH * SEQ * DK];    // [H][S][DK], pre-scaled by 1/sqrt(DK)
__device__ float g_k[NH * SEQ * DK];
__device__ float g_v[NH * SEQ * DK];
__device__ float g_att[SEQ * DIM];      // attention output back in [S, D] layout

// ------------------------------------------------------------------
// SGEMM: C = A[M,K] @ W[K,N] + bias, 128x128 tiles, BK=16, 8x8/thread
// ------------------------------------------------------------------
#define BM 128
#define BN 128
#define BK 16

__device__ __forceinline__ void gemm_body(
    const float* __restrict__ A, const float* __restrict__ W,
    const float* __restrict__ bias, float* __restrict__ C,
    float scale, int scatter)
{
    __shared__ float As[BK][BM];   // A tile stored k-major (transposed)
    __shared__ float Ws[BK][BN];

    const int tid = threadIdx.x;          // 256 threads
    const int tm  = tid >> 4;             // 0..15
    const int tn  = tid & 15;             // 0..15
    const int row0 = blockIdx.y * BM;
    const int col0 = blockIdx.x * BN;

    float acc[8][8];
#pragma unroll
    for (int i = 0; i < 8; ++i)
#pragma unroll
        for (int j = 0; j < 8; ++j) acc[i][j] = 0.0f;

    for (int kt = 0; kt < DIM; kt += BK) {
        // Load A tile: 128 rows x 16 cols = 512 float4, 2 per thread, store transposed
#pragma unroll
        for (int t = 0; t < 2; ++t) {
            int f  = tid + t * 256;
            int r  = f >> 2;
            int c4 = (f & 3) << 2;
            float4 v = *(const float4*)&A[(size_t)(row0 + r) * DIM + kt + c4];
            As[c4 + 0][r] = v.x;
            As[c4 + 1][r] = v.y;
            As[c4 + 2][r] = v.z;
            As[c4 + 3][r] = v.w;
        }
        // Load W tile: 16 rows x 128 cols = 512 float4, 2 per thread
#pragma unroll
        for (int t = 0; t < 2; ++t) {
            int f = tid + t * 256;
            int r = f >> 5;
            int c = (f & 31) << 2;
            *(float4*)&Ws[r][c] = *(const float4*)&W[(size_t)(kt + r) * DIM + col0 + c];
        }
        __syncthreads();

#pragma unroll
        for (int kk = 0; kk < BK; ++kk) {
            float a[8], b[8];
            *(float4*)&a[0] = *(const float4*)&As[kk][tm * 8];
            *(float4*)&a[4] = *(const float4*)&As[kk][tm * 8 + 4];
            *(float4*)&b[0] = *(const float4*)&Ws[kk][tn * 8];
            *(float4*)&b[4] = *(const float4*)&Ws[kk][tn * 8 + 4];
#pragma unroll
            for (int i = 0; i < 8; ++i)
#pragma unroll
                for (int j = 0; j < 8; ++j)
                    acc[i][j] += a[i] * b[j];
        }
        __syncthreads();
    }

    // Epilogue
#pragma unroll
    for (int i = 0; i < 8; ++i) {
        int r = row0 + tm * 8 + i;
#pragma unroll
        for (int j = 0; j < 8; ++j) {
            int c = col0 + tn * 8 + j;
            float v = (acc[i][j] + bias[c]) * scale;
            if (scatter) {
                int h = c >> 7;        // head
                int d = c & 127;       // dim within head
                C[((size_t)h * SEQ + r) * DK + d] = v;
            } else {
                C[(size_t)r * DIM + c] = v;
            }
        }
    }
}

__global__ __launch_bounds__(256) void qkv_gemm(
    const float* __restrict__ x,
    const float* __restrict__ Wq, const float* __restrict__ bq,
    const float* __restrict__ Wk, const float* __restrict__ bk,
    const float* __restrict__ Wv, const float* __restrict__ bv)
{
    int which = blockIdx.z;
    const float* W = (which == 0) ? Wq : (which == 1) ? Wk : Wv;
    const float* b = (which == 0) ? bq : (which == 1) ? bk : bv;
    float* out     = (which == 0) ? g_q : (which == 1) ? g_k : g_v;
    float scale    = (which == 0) ? 0.08838834764831845f : 1.0f;  // 1/sqrt(128) folded into Q
    gemm_body(x, W, b, out, scale, 1);
}

__global__ __launch_bounds__(256) void out_gemm(
    const float* __restrict__ Wo, const float* __restrict__ bo,
    float* __restrict__ out)
{
    gemm_body(g_att, Wo, bo, out, 1.0f, 0);
}

// ------------------------------------------------------------------
// Fused causal flash attention
// One CTA per (head, 64-row q tile). 256 threads = 16x16 grid,
// thread owns a 4x4 score tile and a 4x8 output tile.
// ------------------------------------------------------------------
#define AM 64        // q rows per CTA
#define AN 64        // kv rows per tile
#define QST 68       // padded row stride for d-major Q/K tiles
#define PST 68       // padded row stride for P tile

// dynamic shared layout (floats):
//   Qs[128][QST]  = 8704
//   Ks[128][QST]  = 8704
//   Vs[64][128]   = 8192
//   Ps[64][PST]   = 4352
#define SMEM_FLOATS (128 * QST + 128 * QST + AN * DK + AM * PST)

extern __shared__ float sm_attn[];

__global__ __launch_bounds__(256) void attn_kernel()
{
    float* Qs = sm_attn;
    float* Ks = Qs + 128 * QST;
    float* Vs = Ks + 128 * QST;
    float* Ps = Vs + AN * DK;

    const int tid = threadIdx.x;
    const int tm  = tid >> 4;
    const int tn  = tid & 15;
    const int h   = blockIdx.y;
    const int qi  = blockIdx.x;
    const int q0  = qi * AM;

    const float* qp = g_q + (size_t)h * SEQ * DK;
    const float* kp = g_k + (size_t)h * SEQ * DK;
    const float* vp = g_v + (size_t)h * SEQ * DK;

    // Load Q tile d-major: Qs[d][r]
#pragma unroll
    for (int t = 0; t < 8; ++t) {
        int f = tid + t * 256;
        int r = f >> 5;
        int c = (f & 31) << 2;
        float4 val = *(const float4*)&qp[(size_t)(q0 + r) * DK + c];
        Qs[(c + 0) * QST + r] = val.x;
        Qs[(c + 1) * QST + r] = val.y;
        Qs[(c + 2) * QST + r] = val.z;
        Qs[(c + 3) * QST + r] = val.w;
    }

    float m[4], l[4], o[4][8];
#pragma unroll
    for (int i = 0; i < 4; ++i) {
        m[i] = -1e30f;
        l[i] = 0.0f;
#pragma unroll
        for (int j = 0; j < 8; ++j) o[i][j] = 0.0f;
    }

    const int rowA = tm * 4;   // local q rows rowA..rowA+3
    const int colO = tn * 8;   // output dims colO..colO+7

    for (int jt = 0; jt <= qi; ++jt) {
        __syncthreads();   // previous iteration's PV reads done

        // Load K tile d-major + V tile row-major
#pragma unroll
        for (int t = 0; t < 8; ++t) {
            int f = tid + t * 256;
            int r = f >> 5;
            int c = (f & 31) << 2;
            const float4 kv = *(const float4*)&kp[(size_t)(jt * AN + r) * DK + c];
            Ks[(c + 0) * QST + r] = kv.x;
            Ks[(c + 1) * QST + r] = kv.y;
            Ks[(c + 2) * QST + r] = kv.z;
            Ks[(c + 3) * QST + r] = kv.w;
            *(float4*)&Vs[r * DK + c] = *(const float4*)&vp[(size_t)(jt * AN + r) * DK + c];
        }
        __syncthreads();

        // S = Q K^T (Q already scaled)
        float s[4][4];
#pragma unroll
        for (int i = 0; i < 4; ++i)
#pragma unroll
            for (int j = 0; j < 4; ++j) s[i][j] = 0.0f;

        for (int d = 0; d < DK; ++d) {
            float4 qa = *(const float4*)&Qs[d * QST + rowA];
            float4 kb = *(const float4*)&Ks[d * QST + tn * 4];
            float av[4] = {qa.x, qa.y, qa.z, qa.w};
            float bv[4] = {kb.x, kb.y, kb.z, kb.w};
#pragma unroll
            for (int i = 0; i < 4; ++i)
#pragma unroll
                for (int j = 0; j < 4; ++j)
                    s[i][j] += av[i] * bv[j];
        }

        // Causal mask (only the diagonal tile can have masked entries)
        if (jt == qi) {
#pragma unroll
            for (int i = 0; i < 4; ++i)
#pragma unroll
                for (int j = 0; j < 4; ++j)
                    if (tn * 4 + j > rowA + i) s[i][j] = -1e30f;
        }

        // Online softmax update (16 threads per row, half-warp shfl reduce)
#pragma unroll
        for (int i = 0; i < 4; ++i) {
            float tmax = fmaxf(fmaxf(s[i][0], s[i][1]), fmaxf(s[i][2], s[i][3]));
#pragma unroll
            for (int off = 8; off >= 1; off >>= 1)
                tmax = fmaxf(tmax, __shfl_xor_sync(0xffffffffu, tmax, off));
            float mn = fmaxf(m[i], tmax);
            float alpha = __expf(m[i] - mn);
            float p[4], ps = 0.0f;
#pragma unroll
            for (int j = 0; j < 4; ++j) { p[j] = __expf(s[i][j] - mn); ps += p[j]; }
#pragma unroll
            for (int off = 8; off >= 1; off >>= 1)
                ps += __shfl_xor_sync(0xffffffffu, ps, off);
            l[i] = l[i] * alpha + ps;
            m[i] = mn;
#pragma unroll
            for (int c8 = 0; c8 < 8; ++c8) o[i][c8] *= alpha;
            *(float4*)&Ps[(rowA + i) * PST + tn * 4] = make_float4(p[0], p[1], p[2], p[3]);
        }
        __syncthreads();   // P visible to all

        // O += P @ V
        for (int kk = 0; kk < AN; ++kk) {
            float4 v0 = *(const float4*)&Vs[kk * DK + colO];
            float4 v1 = *(const float4*)&Vs[kk * DK + colO + 4];
#pragma unroll
            for (int i = 0; i < 4; ++i) {
                float pp = Ps[(rowA + i) * PST + kk];
                o[i][0] += pp * v0.x; o[i][1] += pp * v0.y;
                o[i][2] += pp * v0.z; o[i][3] += pp * v0.w;
                o[i][4] += pp * v1.x; o[i][5] += pp * v1.y;
                o[i][6] += pp * v1.z; o[i][7] += pp * v1.w;
            }
        }
    }

    // Normalize and write back in [S, D] layout
#pragma unroll
    for (int i = 0; i < 4; ++i) {
        float inv = 1.0f / l[i];
        int r = q0 + rowA + i;
#pragma unroll
        for (int j = 0; j < 8; ++j)
            g_att[(size_t)r * DIM + h * DK + colO + j] = o[i][j] * inv;
    }
}

// ------------------------------------------------------------------
// Launch
// ------------------------------------------------------------------
extern "C" void kernel_launch(void* const* d_in, const int* in_sizes, int n_in,
                              void* d_out, int out_size)
{
    const float* x  = (const float*)d_in[0];
    const float* Wq = (const float*)d_in[1];
    const float* bq = (const float*)d_in[2];
    const float* Wk = (const float*)d_in[3];
    const float* bk = (const float*)d_in[4];
    const float* Wv = (const float*)d_in[5];
    const float* bv = (const float*)d_in[6];
    const float* Wo = (const float*)d_in[7];
    const float* bo = (const float*)d_in[8];
    float* out = (float*)d_out;

    dim3 blk(256);

    // 1) Q/K/V projections (Q pre-scaled by 1/sqrt(dk))
    qkv_gemm<<<dim3(DIM / BN, SEQ / BM, 3), blk>>>(x, Wq, bq, Wk, bk, Wv, bv);

    // 2) Fused causal flash attention
    size_t smem = SMEM_FLOATS * sizeof(float);  // ~117 KB
    cudaFuncSetAttribute(attn_kernel, cudaFuncAttributeMaxDynamicSharedMemorySize, (int)smem);
    attn_kernel<<<dim3(SEQ / AM, NH), blk, smem>>>();

    // 3) Output projection
    out_gemm<<<dim3(DIM / BN, SEQ / BM), blk>>>(Wo, bo, out);
}

// round 3
// speedup vs baseline: 1.6048x; 1.6048x over previous
#include <cuda_runtime.h>
#include <cuda_bf16.h>
#include <cstdint>
#include <math.h>

// Problem constants
#define SEQ 2048
#define DIM 2048
#define NH  16
#define DK  128

// ------------------------------------------------------------------
// Scratch (device globals — no allocations inside kernel_launch)
// ------------------------------------------------------------------
__device__ float g_q[NH * SEQ * DK];    // [H][S][DK], Q pre-scaled by 1/sqrt(DK)
__device__ float g_k[NH * SEQ * DK];
__device__ float g_v[NH * SEQ * DK];
__device__ float g_att[SEQ * DIM];      // attention output in [S, D] layout

// split-bf16 operands
__device__ __nv_bfloat16 g_a_hi[SEQ * DIM];           // A operand (x, then att)
__device__ __nv_bfloat16 g_a_lo[SEQ * DIM];
__device__ __nv_bfloat16 g_wt_hi[4u * DIM * DIM];     // W^T per matrix, K-major
__device__ __nv_bfloat16 g_wt_lo[4u * DIM * DIM];

// ------------------------------------------------------------------
// Baseline-PTX helpers (all sm_80-level: work on compute_103 target)
// ------------------------------------------------------------------
__device__ __forceinline__ uint32_t smem_u32(const void* p) {
    uint32_t a;
    asm("{ .reg .u64 t; cvta.to.shared.u64 t, %1; cvt.u32.u64 %0, t; }" : "=r"(a) : "l"(p));
    return a;
}

#define CP_ASYNC16(sm, gp) \
    asm volatile("cp.async.cg.shared.global [%0], [%1], 16;" :: "r"(sm), "l"(gp))
#define CP_COMMIT() asm volatile("cp.async.commit_group;" ::: "memory")
#define CP_WAIT1()  asm volatile("cp.async.wait_group 1;" ::: "memory")
#define CP_WAIT0()  asm volatile("cp.async.wait_group 0;" ::: "memory")

#define LDSM_X4(r0, r1, r2, r3, addr) \
    asm volatile("ldmatrix.sync.aligned.m8n8.x4.shared.b16 {%0,%1,%2,%3}, [%4];" \
                 : "=r"(r0), "=r"(r1), "=r"(r2), "=r"(r3) : "r"(addr))

#define MMA16816(c, a, b) \
    asm volatile("mma.sync.aligned.m16n8k16.row.col.f32.bf16.bf16.f32 " \
                 "{%0,%1,%2,%3}, {%4,%5,%6,%7}, {%8,%9}, {%0,%1,%2,%3};" \
                 : "+f"((c)[0]), "+f"((c)[1]), "+f"((c)[2]), "+f"((c)[3]) \
                 : "r"((a)[0]), "r"((a)[1]), "r"((a)[2]), "r"((a)[3]), \
                   "r"((b)[0]), "r"((b)[1]))

// ------------------------------------------------------------------
// Conversion kernels (fp32 -> hi/lo bf16 split)
// ------------------------------------------------------------------
__global__ __launch_bounds__(256) void convert_split(
    const float* __restrict__ in, __nv_bfloat16* __restrict__ hi, __nv_bfloat16* __restrict__ lo)
{
    size_t i = ((size_t)blockIdx.x * 256 + threadIdx.x) * 4;
    float4 v = *(const float4*)(in + i);
    float vv[4] = {v.x, v.y, v.z, v.w};
    __nv_bfloat16 h[4], l[4];
#pragma unroll
    for (int j = 0; j < 4; ++j) {
        h[j] = __float2bfloat16(vv[j]);
        l[j] = __float2bfloat16(vv[j] - __bfloat162float(h[j]));
    }
    *(__nv_bfloat162*)(hi + i)     = __nv_bfloat162(h[0], h[1]);
    *(__nv_bfloat162*)(hi + i + 2) = __nv_bfloat162(h[2], h[3]);
    *(__nv_bfloat162*)(lo + i)     = __nv_bfloat162(l[0], l[1]);
    *(__nv_bfloat162*)(lo + i + 2) = __nv_bfloat162(l[2], l[3]);
}

// W[K,N] -> W^T hi/lo [N,K], optional scale folded in
__global__ __launch_bounds__(256) void convert_split_T(
    const float* __restrict__ W, __nv_bfloat16* __restrict__ thi,
    __nv_bfloat16* __restrict__ tlo, float scale)
{
    __shared__ float tile[32][33];
    int n0 = blockIdx.x * 32, k0 = blockIdx.y * 32;
    int tx = threadIdx.x, ty = threadIdx.y;   // (32, 8)
#pragma unroll
    for (int t = 0; t < 4; ++t)
        tile[ty + 8 * t][tx] = W[(size_t)(k0 + ty + 8 * t) * DIM + n0 + tx] * scale;
    __syncthreads();
#pragma unroll
    for (int t = 0; t < 4; ++t) {
        int r = ty + 8 * t;
        float v = tile[tx][r];
        __nv_bfloat16 h = __float2bfloat16(v);
        __nv_bfloat16 l = __float2bfloat16(v - __bfloat162float(h));
        thi[(size_t)(n0 + r) * DIM + k0 + tx] = h;
        tlo[(size_t)(n0 + r) * DIM + k0 + tx] = l;
    }
}

// ------------------------------------------------------------------
// mma.sync split-bf16 GEMM: out[M,N] = A[M,K] @ B^T[N,K] + bias
// CTA 128x128, 8 warps (warp tile 32x64), KC=64, cp.async double buffer
// ------------------------------------------------------------------
#define TMM 128
#define TNN 128
#define KC 64
#define NCHUNK (DIM / KC)          // 32
#define LSTRIDE 144                 // smem row stride bytes (72 bf16) -> conflict-free
#define TILE_B (128 * LSTRIDE)      // 18432 bytes per tile
#define OFF_AHI 0
#define OFF_ALO (1 * TILE_B)
#define OFF_BHI (2 * TILE_B)
#define OFF_BLO (3 * TILE_B)
#define STAGE_B (4 * TILE_B)        // 73728
#define GEMM_SMEM (2 * STAGE_B)     // 147456

__device__ __forceinline__ void load_chunk(
    uint32_t sbase, const __nv_bfloat16* __restrict__ Ahi, const __nv_bfloat16* __restrict__ Alo,
    const __nv_bfloat16* __restrict__ Bhi, const __nv_bfloat16* __restrict__ Blo,
    int row0, int col0, int k0, int tid)
{
    const int col16 = tid & 7;          // 16B unit within the 128B row payload
    const int rb    = tid >> 3;         // 0..31
    const int kg    = k0 + col16 * 8;   // global k element offset
#pragma unroll
    for (int t = 0; t < 4; ++t) {
        int r = rb + t * 32;
        uint32_t so = r * LSTRIDE + col16 * 16;
        size_t ga = (size_t)(row0 + r) * DIM + kg;
        size_t gb = (size_t)(col0 + r) * DIM + kg;
        CP_ASYNC16(sbase + OFF_AHI + so, Ahi + ga);
        CP_ASYNC16(sbase + OFF_ALO + so, Alo + ga);
        CP_ASYNC16(sbase + OFF_BHI + so, Bhi + gb);
        CP_ASYNC16(sbase + OFF_BLO + so, Blo + gb);
    }
}

__device__ __forceinline__ void gemm_tc_body(
    const __nv_bfloat16* __restrict__ Ahi, const __nv_bfloat16* __restrict__ Alo,
    const __nv_bfloat16* __restrict__ Bhi, const __nv_bfloat16* __restrict__ Blo,
    const float* __restrict__ bias, float bscale,
    float* __restrict__ outp, int scatter)
{
    extern __shared__ char smg[];
    const int tid  = threadIdx.x;
    const int wid  = tid >> 5;
    const int lane = tid & 31;
    const int row0 = blockIdx.y * TMM;
    const int col0 = blockIdx.x * TNN;
    const int wm   = (wid & 3) * 32;    // warp m offset
    const int wn   = (wid >> 2) * 64;   // warp n offset
    const uint32_t sb = smem_u32(smg);

    float c[2][8][4];
#pragma unroll
    for (int mt = 0; mt < 2; ++mt)
#pragma unroll
        for (int nt = 0; nt < 8; ++nt)
#pragma unroll
            for (int j = 0; j < 4; ++j) c[mt][nt][j] = 0.0f;

    // ldmatrix per-lane address components (byte offsets within a tile)
    const uint32_t a_off = (wm + (lane & 15)) * LSTRIDE + (lane >> 4) * 16;
    const uint32_t b_row = wn + (lane & 7) + ((lane >> 4) & 1) * 8;
    const uint32_t b_off = b_row * LSTRIDE + ((lane >> 3) & 1) * 16;

    // prologue: load chunk 0
    load_chunk(sb, Ahi, Alo, Bhi, Blo, row0, col0, 0, tid);
    CP_COMMIT();

    for (int ch = 0; ch < NCHUNK; ++ch) {
        const uint32_t stage = sb + (ch & 1) * STAGE_B;
        if (ch + 1 < NCHUNK) {
            load_chunk(sb + ((ch + 1) & 1) * STAGE_B, Ahi, Alo, Bhi, Blo,
                       row0, col0, (ch + 1) * KC, tid);
            CP_COMMIT();
            CP_WAIT1();
        } else {
            CP_WAIT0();
        }
        __syncthreads();

#pragma unroll
        for (int ks = 0; ks < 4; ++ks) {
            const uint32_t kb = ks * 32;   // 16 bf16 = 32 bytes
            uint32_t ahi[2][4], alo[2][4];
#pragma unroll
            for (int mt = 0; mt < 2; ++mt) {
                uint32_t ad = stage + (uint32_t)(mt * 16 * LSTRIDE) + a_off + kb;
                LDSM_X4(ahi[mt][0], ahi[mt][1], ahi[mt][2], ahi[mt][3], ad + OFF_AHI);
                LDSM_X4(alo[mt][0], alo[mt][1], alo[mt][2], alo[mt][3], ad + OFF_ALO);
            }
            uint32_t bhi[8][2], blo[8][2];
#pragma unroll
            for (int q = 0; q < 4; ++q) {
                uint32_t bd = stage + (uint32_t)(q * 16 * LSTRIDE) + b_off + kb;
                LDSM_X4(bhi[2 * q][0], bhi[2 * q][1], bhi[2 * q + 1][0], bhi[2 * q + 1][1],
                        bd + OFF_BHI);
                LDSM_X4(blo[2 * q][0], blo[2 * q][1], blo[2 * q + 1][0], blo[2 * q + 1][1],
                        bd + OFF_BLO);
            }
#pragma unroll
            for (int mt = 0; mt < 2; ++mt)
#pragma unroll
                for (int nt = 0; nt < 8; ++nt) {
                    MMA16816(c[mt][nt], ahi[mt], bhi[nt]);
                    MMA16816(c[mt][nt], ahi[mt], blo[nt]);
                    MMA16816(c[mt][nt], alo[mt], bhi[nt]);
                }
        }
        __syncthreads();
    }

    // Epilogue: c[mt][nt] regs -> global (+bias, optional head scatter)
#pragma unroll
    for (int mt = 0; mt < 2; ++mt) {
#pragma unroll
        for (int nt = 0; nt < 8; ++nt) {
            int cg = col0 + wn + nt * 8 + (lane & 3) * 2;
            float b0 = bias[cg] * bscale;
            float b1 = bias[cg + 1] * bscale;
            int r0 = row0 + wm + mt * 16 + (lane >> 2);
#pragma unroll
            for (int hh = 0; hh < 2; ++hh) {
                int r = r0 + hh * 8;
                float v0 = c[mt][nt][2 * hh + 0] + b0;
                float v1 = c[mt][nt][2 * hh + 1] + b1;
                if (scatter) {
                    int h = cg >> 7, d0 = cg & 127;
                    float* ob = outp + ((size_t)h * SEQ + r) * DK + d0;
                    ob[0] = v0; ob[1] = v1;
                } else {
                    float* ob = outp + (size_t)r * DIM + cg;
                    ob[0] = v0; ob[1] = v1;
                }
            }
        }
    }
}

__global__ __launch_bounds__(256, 1) void qkv_tc(
    const float* __restrict__ bq, const float* __restrict__ bk, const float* __restrict__ bvv)
{
    int z = blockIdx.z;
    const __nv_bfloat16* Whi = g_wt_hi + (size_t)z * DIM * DIM;
    const __nv_bfloat16* Wlo = g_wt_lo + (size_t)z * DIM * DIM;
    const float* bias = (z == 0) ? bq : (z == 1) ? bk : bvv;
    float* outp = (z == 0) ? g_q : (z == 1) ? g_k : g_v;
    float bscale = (z == 0) ? 0.08838834764831845f : 1.0f;   // bias scale only for Q
    gemm_tc_body(g_a_hi, g_a_lo, Whi, Wlo, bias, bscale, outp, 1);
}

__global__ __launch_bounds__(256, 1) void out_tc(const float* __restrict__ bo, float* __restrict__ out)
{
    gemm_tc_body(g_a_hi, g_a_lo, g_wt_hi + (size_t)3 * DIM * DIM, g_wt_lo + (size_t)3 * DIM * DIM,
                 bo, 1.0f, out, 0);
}

// ------------------------------------------------------------------
// Fused causal flash attention (fp32 SIMT, unchanged from R1)
// ------------------------------------------------------------------
#define AM 64
#define AN 64
#define QST 68
#define PST 68
#define SMEM_FLOATS (128 * QST + 128 * QST + AN * DK + AM * PST)

extern __shared__ float sm_attn[];

__global__ __launch_bounds__(256) void attn_kernel()
{
    float* Qs = sm_attn;
    float* Ks = Qs + 128 * QST;
    float* Vs = Ks + 128 * QST;
    float* Ps = Vs + AN * DK;

    const int tid = threadIdx.x;
    const int tm  = tid >> 4;
    const int tn  = tid & 15;
    const int h   = blockIdx.y;
    const int qi  = blockIdx.x;
    const int q0  = qi * AM;

    const float* qp = g_q + (size_t)h * SEQ * DK;
    const float* kp = g_k + (size_t)h * SEQ * DK;
    const float* vp = g_v + (size_t)h * SEQ * DK;

#pragma unroll
    for (int t = 0; t < 8; ++t) {
        int f = tid + t * 256;
        int r = f >> 5;
        int c = (f & 31) << 2;
        float4 val = *(const float4*)&qp[(size_t)(q0 + r) * DK + c];
        Qs[(c + 0) * QST + r] = val.x;
        Qs[(c + 1) * QST + r] = val.y;
        Qs[(c + 2) * QST + r] = val.z;
        Qs[(c + 3) * QST + r] = val.w;
    }

    float m[4], l[4], o[4][8];
#pragma unroll
    for (int i = 0; i < 4; ++i) {
        m[i] = -1e30f;
        l[i] = 0.0f;
#pragma unroll
        for (int j = 0; j < 8; ++j) o[i][j] = 0.0f;
    }

    const int rowA = tm * 4;
    const int colO = tn * 8;

    for (int jt = 0; jt <= qi; ++jt) {
        __syncthreads();
#pragma unroll
        for (int t = 0; t < 8; ++t) {
            int f = tid + t * 256;
            int r = f >> 5;
            int c = (f & 31) << 2;
            const float4 kv = *(const float4*)&kp[(size_t)(jt * AN + r) * DK + c];
            Ks[(c + 0) * QST + r] = kv.x;
            Ks[(c + 1) * QST + r] = kv.y;
            Ks[(c + 2) * QST + r] = kv.z;
            Ks[(c + 3) * QST + r] = kv.w;
            *(float4*)&Vs[r * DK + c] = *(const float4*)&vp[(size_t)(jt * AN + r) * DK + c];
        }
        __syncthreads();

        float s[4][4];
#pragma unroll
        for (int i = 0; i < 4; ++i)
#pragma unroll
            for (int j = 0; j < 4; ++j) s[i][j] = 0.0f;

        for (int d = 0; d < DK; ++d) {
            float4 qa = *(const float4*)&Qs[d * QST + rowA];
            float4 kb = *(const float4*)&Ks[d * QST + tn * 4];
            float av[4] = {qa.x, qa.y, qa.z, qa.w};
            float bv[4] = {kb.x, kb.y, kb.z, kb.w};
#pragma unroll
            for (int i = 0; i < 4; ++i)
#pragma unroll
                for (int j = 0; j < 4; ++j)
                    s[i][j] += av[i] * bv[j];
        }

        if (jt == qi) {
#pragma unroll
            for (int i = 0; i < 4; ++i)
#pragma unroll
                for (int j = 0; j < 4; ++j)
                    if (tn * 4 + j > rowA + i) s[i][j] = -1e30f;
        }

#pragma unroll
        for (int i = 0; i < 4; ++i) {
            float tmax = fmaxf(fmaxf(s[i][0], s[i][1]), fmaxf(s[i][2], s[i][3]));
#pragma unroll
            for (int off = 8; off >= 1; off >>= 1)
                tmax = fmaxf(tmax, __shfl_xor_sync(0xffffffffu, tmax, off));
            float mn = fmaxf(m[i], tmax);
            float alpha = __expf(m[i] - mn);
            float p[4], ps = 0.0f;
#pragma unroll
            for (int j = 0; j < 4; ++j) { p[j] = __expf(s[i][j] - mn); ps += p[j]; }
#pragma unroll
            for (int off = 8; off >= 1; off >>= 1)
                ps += __shfl_xor_sync(0xffffffffu, ps, off);
            l[i] = l[i] * alpha + ps;
            m[i] = mn;
#pragma unroll
            for (int c8 = 0; c8 < 8; ++c8) o[i][c8] *= alpha;
            *(float4*)&Ps[(rowA + i) * PST + tn * 4] = make_float4(p[0], p[1], p[2], p[3]);
        }
        __syncthreads();

        for (int kk = 0; kk < AN; ++kk) {
            float4 v0 = *(const float4*)&Vs[kk * DK + colO];
            float4 v1 = *(const float4*)&Vs[kk * DK + colO + 4];
#pragma unroll
            for (int i = 0; i < 4; ++i) {
                float pp = Ps[(rowA + i) * PST + kk];
                o[i][0] += pp * v0.x; o[i][1] += pp * v0.y;
                o[i][2] += pp * v0.z; o[i][3] += pp * v0.w;
                o[i][4] += pp * v1.x; o[i][5] += pp * v1.y;
                o[i][6] += pp * v1.z; o[i][7] += pp * v1.w;
            }
        }
    }

#pragma unroll
    for (int i = 0; i < 4; ++i) {
        float inv = 1.0f / l[i];
        int r = q0 + rowA + i;
#pragma unroll
        for (int j = 0; j < 8; ++j)
            g_att[(size_t)r * DIM + h * DK + colO + j] = o[i][j] * inv;
    }
}

// ------------------------------------------------------------------
// Launch
// ------------------------------------------------------------------
extern "C" void kernel_launch(void* const* d_in, const int* in_sizes, int n_in,
                              void* d_out, int out_size)
{
    const float* x  = (const float*)d_in[0];
    const float* Wq = (const float*)d_in[1];
    const float* bq = (const float*)d_in[2];
    const float* Wk = (const float*)d_in[3];
    const float* bk = (const float*)d_in[4];
    const float* Wv = (const float*)d_in[5];
    const float* bv = (const float*)d_in[6];
    const float* Wo = (const float*)d_in[7];
    const float* bo = (const float*)d_in[8];
    float* out = (float*)d_out;

    __nv_bfloat16 *a_hi, *a_lo, *wt_hi, *wt_lo;
    cudaGetSymbolAddress((void**)&a_hi, g_a_hi);
    cudaGetSymbolAddress((void**)&a_lo, g_a_lo);
    cudaGetSymbolAddress((void**)&wt_hi, g_wt_hi);
    cudaGetSymbolAddress((void**)&wt_lo, g_wt_lo);
    float* att;
    cudaGetSymbolAddress((void**)&att, g_att);

    cudaFuncSetAttribute(qkv_tc, cudaFuncAttributeMaxDynamicSharedMemorySize, GEMM_SMEM);
    cudaFuncSetAttribute(out_tc, cudaFuncAttributeMaxDynamicSharedMemorySize, GEMM_SMEM);
    size_t asmem = SMEM_FLOATS * sizeof(float);
    cudaFuncSetAttribute(attn_kernel, cudaFuncAttributeMaxDynamicSharedMemorySize, (int)asmem);

    const float qscale = 0.08838834764831845f;   // 1/sqrt(128)
    dim3 tblk(32, 8);
    dim3 tgrd(DIM / 32, DIM / 32);

    // 1) operand conversions (Wq scaled by 1/sqrt(dk); bq scaled at epilogue)
    convert_split<<<SEQ * DIM / 1024, 256>>>(x, a_hi, a_lo);
    convert_split_T<<<tgrd, tblk>>>(Wq, wt_hi + (size_t)0 * DIM * DIM, wt_lo + (size_t)0 * DIM * DIM, qscale);
    convert_split_T<<<tgrd, tblk>>>(Wk, wt_hi + (size_t)1 * DIM * DIM, wt_lo + (size_t)1 * DIM * DIM, 1.0f);
    convert_split_T<<<tgrd, tblk>>>(Wv, wt_hi + (size_t)2 * DIM * DIM, wt_lo + (size_t)2 * DIM * DIM, 1.0f);
    convert_split_T<<<tgrd, tblk>>>(Wo, wt_hi + (size_t)3 * DIM * DIM, wt_lo + (size_t)3 * DIM * DIM, 1.0f);

    // 2) Q/K/V projections on tensor cores (mma.sync)
    qkv_tc<<<dim3(DIM / TNN, SEQ / TMM, 3), 256, GEMM_SMEM>>>(bq, bk, bv);

    // 3) fused causal flash attention (fp32 SIMT)
    attn_kernel<<<dim3(SEQ / AM, NH), 256, asmem>>>();

    // 4) attention output -> split bf16 -> output projection
    convert_split<<<SEQ * DIM / 1024, 256>>>(att, a_hi, a_lo);
    out_tc<<<dim3(DIM / TNN, SEQ / TMM), 256, GEMM_SMEM>>>(bo, out);
}

// round 4
// speedup vs baseline: 2.6647x; 1.6605x over previous
#include <cuda_runtime.h>
#include <cuda_bf16.h>
#include <cstdint>
#include <string.h>
#include <math.h>

// Problem constants
#define SEQ 2048
#define DIM 2048
#define NH  16
#define DK  128

// ------------------------------------------------------------------
// Scratch (device globals)
// ------------------------------------------------------------------
__device__ __nv_bfloat16 g_a_hi[SEQ * DIM];          // A operand (x, then att)
__device__ __nv_bfloat16 g_a_lo[SEQ * DIM];
__device__ __nv_bfloat16 g_wt_hi[4u * DIM * DIM];    // W^T per matrix, K-major
__device__ __nv_bfloat16 g_wt_lo[4u * DIM * DIM];
__device__ __nv_bfloat16 g_q_hi[NH * SEQ * DK], g_q_lo[NH * SEQ * DK];
__device__ __nv_bfloat16 g_k_hi[NH * SEQ * DK], g_k_lo[NH * SEQ * DK];
__device__ __nv_bfloat16 g_v_hi[NH * SEQ * DK], g_v_lo[NH * SEQ * DK];
__device__ __nv_bfloat16 g_vt_hi[NH * DK * SEQ], g_vt_lo[NH * DK * SEQ];  // V^T [H][dk][S]

// ------------------------------------------------------------------
// Baseline-PTX helpers (sm_80-level)
// ------------------------------------------------------------------
__device__ __forceinline__ uint32_t smem_u32(const void* p) {
    uint32_t a;
    asm("{ .reg .u64 t; cvta.to.shared.u64 t, %1; cvt.u32.u64 %0, t; }" : "=r"(a) : "l"(p));
    return a;
}

#define CP_ASYNC16(sm, gp) \
    asm volatile("cp.async.cg.shared.global [%0], [%1], 16;" :: "r"(sm), "l"(gp))
#define CP_COMMIT() asm volatile("cp.async.commit_group;" ::: "memory")
#define CP_WAIT1()  asm volatile("cp.async.wait_group 1;" ::: "memory")
#define CP_WAIT0()  asm volatile("cp.async.wait_group 0;" ::: "memory")

#define LDSM_X4(r0, r1, r2, r3, addr) \
    asm volatile("ldmatrix.sync.aligned.m8n8.x4.shared.b16 {%0,%1,%2,%3}, [%4];" \
                 : "=r"(r0), "=r"(r1), "=r"(r2), "=r"(r3) : "r"(addr))

#define MMA16816(c, a, b) \
    asm volatile("mma.sync.aligned.m16n8k16.row.col.f32.bf16.bf16.f32 " \
                 "{%0,%1,%2,%3}, {%4,%5,%6,%7}, {%8,%9}, {%0,%1,%2,%3};" \
                 : "+f"((c)[0]), "+f"((c)[1]), "+f"((c)[2]), "+f"((c)[3]) \
                 : "r"((a)[0]), "r"((a)[1]), "r"((a)[2]), "r"((a)[3]), \
                   "r"((b)[0]), "r"((b)[1]))

__device__ __forceinline__ uint32_t b2u(__nv_bfloat162 v) {
    uint32_t u; memcpy(&u, &v, 4); return u;
}

// ------------------------------------------------------------------
// Conversion kernels
// ------------------------------------------------------------------
__global__ __launch_bounds__(256) void convert_split(
    const float* __restrict__ in, __nv_bfloat16* __restrict__ hi, __nv_bfloat16* __restrict__ lo)
{
    size_t i = ((size_t)blockIdx.x * 256 + threadIdx.x) * 4;
    float4 v = *(const float4*)(in + i);
    float vv[4] = {v.x, v.y, v.z, v.w};
    __nv_bfloat16 h[4], l[4];
#pragma unroll
    for (int j = 0; j < 4; ++j) {
        h[j] = __float2bfloat16(vv[j]);
        l[j] = __float2bfloat16(vv[j] - __bfloat162float(h[j]));
    }
    *(__nv_bfloat162*)(hi + i)     = __nv_bfloat162(h[0], h[1]);
    *(__nv_bfloat162*)(hi + i + 2) = __nv_bfloat162(h[2], h[3]);
    *(__nv_bfloat162*)(lo + i)     = __nv_bfloat162(l[0], l[1]);
    *(__nv_bfloat162*)(lo + i + 2) = __nv_bfloat162(l[2], l[3]);
}

__global__ __launch_bounds__(256) void convert_split_T(
    const float* __restrict__ W, __nv_bfloat16* __restrict__ thi,
    __nv_bfloat16* __restrict__ tlo, float scale)
{
    __shared__ float tile[32][33];
    int n0 = blockIdx.x * 32, k0 = blockIdx.y * 32;
    int tx = threadIdx.x, ty = threadIdx.y;   // (32, 8)
#pragma unroll
    for (int t = 0; t < 4; ++t)
        tile[ty + 8 * t][tx] = W[(size_t)(k0 + ty + 8 * t) * DIM + n0 + tx] * scale;
    __syncthreads();
#pragma unroll
    for (int t = 0; t < 4; ++t) {
        int r = ty + 8 * t;
        float v = tile[tx][r];
        __nv_bfloat16 h = __float2bfloat16(v);
        __nv_bfloat16 l = __float2bfloat16(v - __bfloat162float(h));
        thi[(size_t)(n0 + r) * DIM + k0 + tx] = h;
        tlo[(size_t)(n0 + r) * DIM + k0 + tx] = l;
    }
}

// V [H][S][dk] hi/lo -> V^T [H][dk][S] hi/lo
__global__ __launch_bounds__(256) void vt_transpose()
{
    __shared__ __nv_bfloat16 th[32][33], tl[32][33];
    int d0 = blockIdx.x * 32, s0 = blockIdx.y * 32, h = blockIdx.z;
    int tx = threadIdx.x, ty = threadIdx.y;   // (32, 8)
    const __nv_bfloat16* vh = g_v_hi + (size_t)h * SEQ * DK;
    const __nv_bfloat16* vl = g_v_lo + (size_t)h * SEQ * DK;
#pragma unroll
    for (int t = 0; t < 4; ++t) {
        int s = s0 + ty + 8 * t;
        th[ty + 8 * t][tx] = vh[(size_t)s * DK + d0 + tx];
        tl[ty + 8 * t][tx] = vl[(size_t)s * DK + d0 + tx];
    }
    __syncthreads();
    __nv_bfloat16* oh = g_vt_hi + (size_t)h * DK * SEQ;
    __nv_bfloat16* ol = g_vt_lo + (size_t)h * DK * SEQ;
#pragma unroll
    for (int t = 0; t < 4; ++t) {
        int d = d0 + ty + 8 * t;
        oh[(size_t)d * SEQ + s0 + tx] = th[tx][ty + 8 * t];
        ol[(size_t)d * SEQ + s0 + tx] = tl[tx][ty + 8 * t];
    }
}

// ------------------------------------------------------------------
// mma.sync split-bf16 GEMM (CTA 128x128, KC=64, cp.async double buffer)
// ------------------------------------------------------------------
#define TMM 128
#define TNN 128
#define KC 64
#define NCHUNK (DIM / KC)
#define LSTRIDE 144
#define TILE_B (128 * LSTRIDE)
#define OFF_AHI 0
#define OFF_ALO (1 * TILE_B)
#define OFF_BHI (2 * TILE_B)
#define OFF_BLO (3 * TILE_B)
#define STAGE_B (4 * TILE_B)
#define GEMM_SMEM (2 * STAGE_B)

__device__ __forceinline__ void load_chunk(
    uint32_t sbase, const __nv_bfloat16* __restrict__ Ahi, const __nv_bfloat16* __restrict__ Alo,
    const __nv_bfloat16* __restrict__ Bhi, const __nv_bfloat16* __restrict__ Blo,
    int row0, int col0, int k0, int tid)
{
    const int col16 = tid & 7;
    const int rb    = tid >> 3;
    const int kg    = k0 + col16 * 8;
#pragma unroll
    for (int t = 0; t < 4; ++t) {
        int r = rb + t * 32;
        uint32_t so = r * LSTRIDE + col16 * 16;
        size_t ga = (size_t)(row0 + r) * DIM + kg;
        size_t gb = (size_t)(col0 + r) * DIM + kg;
        CP_ASYNC16(sbase + OFF_AHI + so, Ahi + ga);
        CP_ASYNC16(sbase + OFF_ALO + so, Alo + ga);
        CP_ASYNC16(sbase + OFF_BHI + so, Bhi + gb);
        CP_ASYNC16(sbase + OFF_BLO + so, Blo + gb);
    }
}

// scatter=1: write bf16 hi/lo split to [H][S][DK] arrays; scatter=0: fp32 [S][DIM]
__device__ __forceinline__ void gemm_tc_body(
    const __nv_bfloat16* __restrict__ Ahi, const __nv_bfloat16* __restrict__ Alo,
    const __nv_bfloat16* __restrict__ Bhi, const __nv_bfloat16* __restrict__ Blo,
    const float* __restrict__ bias, float bscale,
    float* __restrict__ outp, __nv_bfloat16* __restrict__ ohi, __nv_bfloat16* __restrict__ olo,
    int scatter)
{
    extern __shared__ char smg[];
    const int tid  = threadIdx.x;
    const int wid  = tid >> 5;
    const int lane = tid & 31;
    const int row0 = blockIdx.y * TMM;
    const int col0 = blockIdx.x * TNN;
    const int wm   = (wid & 3) * 32;
    const int wn   = (wid >> 2) * 64;
    const uint32_t sb = smem_u32(smg);

    float c[2][8][4];
#pragma unroll
    for (int mt = 0; mt < 2; ++mt)
#pragma unroll
        for (int nt = 0; nt < 8; ++nt)
#pragma unroll
            for (int j = 0; j < 4; ++j) c[mt][nt][j] = 0.0f;

    const uint32_t a_off = (wm + (lane & 15)) * LSTRIDE + (lane >> 4) * 16;
    const uint32_t b_row = wn + (lane & 7) + ((lane >> 4) & 1) * 8;
    const uint32_t b_off = b_row * LSTRIDE + ((lane >> 3) & 1) * 16;

    load_chunk(sb, Ahi, Alo, Bhi, Blo, row0, col0, 0, tid);
    CP_COMMIT();

    for (int ch = 0; ch < NCHUNK; ++ch) {
        const uint32_t stage = sb + (ch & 1) * STAGE_B;
        if (ch + 1 < NCHUNK) {
            load_chunk(sb + ((ch + 1) & 1) * STAGE_B, Ahi, Alo, Bhi, Blo,
                       row0, col0, (ch + 1) * KC, tid);
            CP_COMMIT();
            CP_WAIT1();
        } else {
            CP_WAIT0();
        }
        __syncthreads();

#pragma unroll
        for (int ks = 0; ks < 4; ++ks) {
            const uint32_t kb = ks * 32;
            uint32_t ahi[2][4], alo[2][4];
#pragma unroll
            for (int mt = 0; mt < 2; ++mt) {
                uint32_t ad = stage + (uint32_t)(mt * 16 * LSTRIDE) + a_off + kb;
                LDSM_X4(ahi[mt][0], ahi[mt][1], ahi[mt][2], ahi[mt][3], ad + OFF_AHI);
                LDSM_X4(alo[mt][0], alo[mt][1], alo[mt][2], alo[mt][3], ad + OFF_ALO);
            }
            uint32_t bhi[8][2], blo[8][2];
#pragma unroll
            for (int q = 0; q < 4; ++q) {
                uint32_t bd = stage + (uint32_t)(q * 16 * LSTRIDE) + b_off + kb;
                LDSM_X4(bhi[2 * q][0], bhi[2 * q][1], bhi[2 * q + 1][0], bhi[2 * q + 1][1],
                        bd + OFF_BHI);
                LDSM_X4(blo[2 * q][0], blo[2 * q][1], blo[2 * q + 1][0], blo[2 * q + 1][1],
                        bd + OFF_BLO);
            }
#pragma unroll
            for (int mt = 0; mt < 2; ++mt)
#pragma unroll
                for (int nt = 0; nt < 8; ++nt) {
                    MMA16816(c[mt][nt], ahi[mt], bhi[nt]);
                    MMA16816(c[mt][nt], ahi[mt], blo[nt]);
                    MMA16816(c[mt][nt], alo[mt], bhi[nt]);
                }
        }
        __syncthreads();
    }

#pragma unroll
    for (int mt = 0; mt < 2; ++mt) {
#pragma unroll
        for (int nt = 0; nt < 8; ++nt) {
            int cg = col0 + wn + nt * 8 + (lane & 3) * 2;
            float b0 = bias[cg] * bscale;
            float b1 = bias[cg + 1] * bscale;
            int r0 = row0 + wm + mt * 16 + (lane >> 2);
#pragma unroll
            for (int hh = 0; hh < 2; ++hh) {
                int r = r0 + hh * 8;
                float v0 = c[mt][nt][2 * hh + 0] + b0;
                float v1 = c[mt][nt][2 * hh + 1] + b1;
                if (scatter) {
                    int hd = cg >> 7, d0 = cg & 127;
                    size_t base = ((size_t)hd * SEQ + r) * DK + d0;
                    __nv_bfloat16 h0 = __float2bfloat16(v0);
                    __nv_bfloat16 h1 = __float2bfloat16(v1);
                    __nv_bfloat16 l0 = __float2bfloat16(v0 - __bfloat162float(h0));
                    __nv_bfloat16 l1 = __float2bfloat16(v1 - __bfloat162float(h1));
                    *(__nv_bfloat162*)(ohi + base) = __nv_bfloat162(h0, h1);
                    *(__nv_bfloat162*)(olo + base) = __nv_bfloat162(l0, l1);
                } else {
                    float* ob = outp + (size_t)r * DIM + cg;
                    ob[0] = v0; ob[1] = v1;
                }
            }
        }
    }
}

__global__ __launch_bounds__(256, 1) void qkv_tc(
    const float* __restrict__ bq, const float* __restrict__ bk, const float* __restrict__ bvv)
{
    int z = blockIdx.z;
    const __nv_bfloat16* Whi = g_wt_hi + (size_t)z * DIM * DIM;
    const __nv_bfloat16* Wlo = g_wt_lo + (size_t)z * DIM * DIM;
    const float* bias = (z == 0) ? bq : (z == 1) ? bk : bvv;
    __nv_bfloat16* ohi = (z == 0) ? g_q_hi : (z == 1) ? g_k_hi : g_v_hi;
    __nv_bfloat16* olo = (z == 0) ? g_q_lo : (z == 1) ? g_k_lo : g_v_lo;
    float bscale = (z == 0) ? 0.08838834764831845f : 1.0f;
    gemm_tc_body(g_a_hi, g_a_lo, Whi, Wlo, bias, bscale, nullptr, ohi, olo, 1);
}

__global__ __launch_bounds__(256, 1) void out_tc(const float* __restrict__ bo, float* __restrict__ out)
{
    gemm_tc_body(g_a_hi, g_a_lo, g_wt_hi + (size_t)3 * DIM * DIM, g_wt_lo + (size_t)3 * DIM * DIM,
                 bo, 1.0f, out, nullptr, nullptr, 0);
}

// ------------------------------------------------------------------
// mma.sync split-bf16 causal flash attention
// CTA: 128 q-rows x 1 head. 8 warps x 16 rows. KV tiles of 64.
// ------------------------------------------------------------------
#define QT 128
#define KT 64
#define QSTR 272                  // 256B payload + 16B pad (odd 16B multiple)
#define VSTR 144                  // 128B payload + 16B pad
#define QB_HI 0
#define QB_LO (128 * QSTR)        // 34816
#define QB_TOT (2 * 128 * QSTR)   // 69632
#define SK_HI 0
#define SK_LO (64 * QSTR)         // 17408
#define SV_HI (2 * 64 * QSTR)     // 34816
#define SV_LO (SV_HI + 128 * VSTR)// 53248
#define STAGE_SZ (SV_LO + 128 * VSTR)  // 71680
#define ATTN_SMEM (QB_TOT + 2 * STAGE_SZ)  // 212992

__device__ __forceinline__ void attn_load_kv(uint32_t st, int h, int kv0, int tid)
{
    const __nv_bfloat16* kh = g_k_hi + ((size_t)h * SEQ + kv0) * DK;
    const __nv_bfloat16* kl = g_k_lo + ((size_t)h * SEQ + kv0) * DK;
    {
        int r = tid >> 2;
#pragma unroll
        for (int i = 0; i < 4; ++i) {
            int u = (tid & 3) * 4 + i;
            CP_ASYNC16(st + SK_HI + r * QSTR + u * 16, kh + (size_t)r * DK + u * 8);
            CP_ASYNC16(st + SK_LO + r * QSTR + u * 16, kl + (size_t)r * DK + u * 8);
        }
    }
    const __nv_bfloat16* vh = g_vt_hi + (size_t)h * DK * SEQ + kv0;
    const __nv_bfloat16* vl = g_vt_lo + (size_t)h * DK * SEQ + kv0;
    {
        int d = tid >> 1;
#pragma unroll
        for (int i = 0; i < 4; ++i) {
            int u = (tid & 1) * 4 + i;
            CP_ASYNC16(st + SV_HI + d * VSTR + u * 16, vh + (size_t)d * SEQ + u * 8);
            CP_ASYNC16(st + SV_LO + d * VSTR + u * 16, vl + (size_t)d * SEQ + u * 8);
        }
    }
}

__global__ __launch_bounds__(256, 1) void attn_mma()
{
    extern __shared__ char sma[];
    const uint32_t sb = smem_u32(sma);
    const int tid  = threadIdx.x;
    const int wid  = tid >> 5;
    const int lane = tid & 31;
    const int h    = blockIdx.y;
    const int qi   = 15 - blockIdx.x;      // heavy tiles first
    const int q0   = qi * QT;
    const int ntiles = 2 * (qi + 1);

    // prologue: Q tile + stage 0 KV, one commit group
    {
        const __nv_bfloat16* qh = g_q_hi + ((size_t)h * SEQ + q0) * DK;
        const __nv_bfloat16* ql = g_q_lo + ((size_t)h * SEQ + q0) * DK;
        int r = tid >> 1;
#pragma unroll
        for (int i = 0; i < 8; ++i) {
            int u = (tid & 1) * 8 + i;
            CP_ASYNC16(sb + QB_HI + r * QSTR + u * 16, qh + (size_t)r * DK + u * 8);
            CP_ASYNC16(sb + QB_LO + r * QSTR + u * 16, ql + (size_t)r * DK + u * 8);
        }
        attn_load_kv(sb + QB_TOT, h, 0, tid);
        CP_COMMIT();
    }

    // per-lane fragment address components
    const uint32_t a_off  = (wid * 16 + (lane & 15)) * QSTR + (lane >> 4) * 16;
    const uint32_t bk_off = ((lane & 7) + ((lane >> 4) & 1) * 8) * QSTR + ((lane >> 3) & 1) * 16;
    const uint32_t bv_off = ((lane & 7) + ((lane >> 4) & 1) * 8) * VSTR + ((lane >> 3) & 1) * 16;

    const int row0_abs = q0 + wid * 16 + (lane >> 2);  // this thread's row 0
    const int rowmax   = q0 + wid * 16 + 15;           // warp's last row

    float o[16][4];
#pragma unroll
    for (int nt = 0; nt < 16; ++nt)
#pragma unroll
        for (int j = 0; j < 4; ++j) o[nt][j] = 0.0f;
    float m0 = -1e4f, m1 = -1e4f, l0 = 0.0f, l1 = 0.0f;

    for (int jt = 0; jt < ntiles; ++jt) {
        if (jt + 1 < ntiles) {
            attn_load_kv(sb + QB_TOT + ((jt + 1) & 1) * STAGE_SZ, h, (jt + 1) * KT, tid);
            CP_COMMIT();
            CP_WAIT1();
        } else {
            CP_WAIT0();
        }
        __syncthreads();

        const int kv0 = jt * KT;
        if (kv0 <= rowmax) {
            const uint32_t st = sb + QB_TOT + (jt & 1) * STAGE_SZ;

            // ---- S = Q K^T (split: hh + hl + lh) ----
            float s[8][4];
#pragma unroll
            for (int nt = 0; nt < 8; ++nt)
#pragma unroll
                for (int j = 0; j < 4; ++j) s[nt][j] = 0.0f;

#pragma unroll
            for (int ks = 0; ks < 8; ++ks) {
                uint32_t ah[4], al[4];
                LDSM_X4(ah[0], ah[1], ah[2], ah[3], sb + QB_HI + a_off + ks * 32);
                LDSM_X4(al[0], al[1], al[2], al[3], sb + QB_LO + a_off + ks * 32);
                uint32_t bh[8][2], bl[8][2];
#pragma unroll
                for (int q = 0; q < 4; ++q) {
                    uint32_t ba = st + SK_HI + bk_off + q * (16 * QSTR) + ks * 32;
                    LDSM_X4(bh[2 * q][0], bh[2 * q][1], bh[2 * q + 1][0], bh[2 * q + 1][1], ba);
                    LDSM_X4(bl[2 * q][0], bl[2 * q][1], bl[2 * q + 1][0], bl[2 * q + 1][1],
                            ba + (SK_LO - SK_HI));
                }
#pragma unroll
                for (int nt = 0; nt < 8; ++nt) MMA16816(s[nt], ah, bh[nt]);
#pragma unroll
                for (int nt = 0; nt < 8; ++nt) MMA16816(s[nt], ah, bl[nt]);
#pragma unroll
                for (int nt = 0; nt < 8; ++nt) MMA16816(s[nt], al, bh[nt]);
            }

            // ---- causal mask ----
            if (kv0 + KT - 1 > q0 + wid * 16) {
#pragma unroll
                for (int nt = 0; nt < 8; ++nt) {
                    int cb = kv0 + nt * 8 + (lane & 3) * 2;
#pragma unroll
                    for (int j = 0; j < 4; ++j) {
                        int col = cb + (j & 1);
                        int row = row0_abs + (j >> 1) * 8;
                        if (col > row) s[nt][j] = -1e30f;
                    }
                }
            }

            // ---- online softmax ----
            float tm0 = -1e30f, tm1 = -1e30f;
#pragma unroll
            for (int nt = 0; nt < 8; ++nt) {
                tm0 = fmaxf(tm0, fmaxf(s[nt][0], s[nt][1]));
                tm1 = fmaxf(tm1, fmaxf(s[nt][2], s[nt][3]));
            }
            tm0 = fmaxf(tm0, __shfl_xor_sync(0xffffffffu, tm0, 1));
            tm0 = fmaxf(tm0, __shfl_xor_sync(0xffffffffu, tm0, 2));
            tm1 = fmaxf(tm1, __shfl_xor_sync(0xffffffffu, tm1, 1));
            tm1 = fmaxf(tm1, __shfl_xor_sync(0xffffffffu, tm1, 2));
            float mn0 = fmaxf(fmaxf(m0, tm0), -1e4f);
            float mn1 = fmaxf(fmaxf(m1, tm1), -1e4f);
            float al0 = __expf(m0 - mn0), al1 = __expf(m1 - mn1);
            m0 = mn0; m1 = mn1;
            float ls0 = 0.0f, ls1 = 0.0f;
#pragma unroll
            for (int nt = 0; nt < 8; ++nt) {
                s[nt][0] = __expf(s[nt][0] - mn0);
                s[nt][1] = __expf(s[nt][1] - mn0);
                s[nt][2] = __expf(s[nt][2] - mn1);
                s[nt][3] = __expf(s[nt][3] - mn1);
                ls0 += s[nt][0] + s[nt][1];
                ls1 += s[nt][2] + s[nt][3];
            }
            l0 = l0 * al0 + ls0;
            l1 = l1 * al1 + ls1;
#pragma unroll
            for (int nt = 0; nt < 16; ++nt) {
                o[nt][0] *= al0; o[nt][1] *= al0;
                o[nt][2] *= al1; o[nt][3] *= al1;
            }

            // ---- pack P into PV A-frags (hi + lo) ----
            uint32_t aph[4][4], apl[4][4];
#pragma unroll
            for (int pr = 0; pr < 4; ++pr) {
#pragma unroll
                for (int half = 0; half < 2; ++half) {
                    int nt = 2 * pr + half;
                    __nv_bfloat162 h01 = __floats2bfloat162_rn(s[nt][0], s[nt][1]);
                    __nv_bfloat162 h23 = __floats2bfloat162_rn(s[nt][2], s[nt][3]);
                    __nv_bfloat162 l01 = __floats2bfloat162_rn(
                        s[nt][0] - __bfloat162float(h01.x), s[nt][1] - __bfloat162float(h01.y));
                    __nv_bfloat162 l23 = __floats2bfloat162_rn(
                        s[nt][2] - __bfloat162float(h23.x), s[nt][3] - __bfloat162float(h23.y));
                    aph[pr][2 * half + 0] = b2u(h01);
                    aph[pr][2 * half + 1] = b2u(h23);
                    apl[pr][2 * half + 0] = b2u(l01);
                    apl[pr][2 * half + 1] = b2u(l23);
                }
            }

            // ---- O += P V (split: hh + hl + lh) ----
#pragma unroll
            for (int kp = 0; kp < 4; ++kp) {
#pragma unroll
                for (int half = 0; half < 2; ++half) {
                    uint32_t vh[8][2], vl[8][2];
#pragma unroll
                    for (int q = 0; q < 4; ++q) {
                        uint32_t ba = st + SV_HI + bv_off + (half * 4 + q) * (16 * VSTR) + kp * 32;
                        LDSM_X4(vh[2 * q][0], vh[2 * q][1], vh[2 * q + 1][0], vh[2 * q + 1][1], ba);
                        LDSM_X4(vl[2 * q][0], vl[2 * q][1], vl[2 * q + 1][0], vl[2 * q + 1][1],
                                ba + (SV_LO - SV_HI));
                    }
#pragma unroll
                    for (int nt = 0; nt < 8; ++nt) {
                        int on = half * 8 + nt;
                        MMA16816(o[on], aph[kp], vh[nt]);
                        MMA16816(o[on], aph[kp], vl[nt]);
                        MMA16816(o[on], apl[kp], vh[nt]);
                    }
                }
            }
        }
        __syncthreads();
    }

    // ---- epilogue: normalize, split to bf16 hi/lo, write att into A operand ----
    l0 += __shfl_xor_sync(0xffffffffu, l0, 1);
    l0 += __shfl_xor_sync(0xffffffffu, l0, 2);
    l1 += __shfl_xor_sync(0xffffffffu, l1, 1);
    l1 += __shfl_xor_sync(0xffffffffu, l1, 2);
    float inv0 = 1.0f / l0, inv1 = 1.0f / l1;

    const int r0 = row0_abs;
    const int r1 = row0_abs + 8;
#pragma unroll
    for (int nt = 0; nt < 16; ++nt) {
        int d = h * DK + nt * 8 + (lane & 3) * 2;
        float v00 = o[nt][0] * inv0, v01 = o[nt][1] * inv0;
        float v10 = o[nt][2] * inv1, v11 = o[nt][3] * inv1;
        __nv_bfloat162 h0 = __floats2bfloat162_rn(v00, v01);
        __nv_bfloat162 l0b = __floats2bfloat162_rn(v00 - __bfloat162float(h0.x),
                                                   v01 - __bfloat162float(h0.y));
        __nv_bfloat162 h1 = __floats2bfloat162_rn(v10, v11);
        __nv_bfloat162 l1b = __floats2bfloat162_rn(v10 - __bfloat162float(h1.x),
                                                   v11 - __bfloat162float(h1.y));
        *(__nv_bfloat162*)(g_a_hi + (size_t)r0 * DIM + d) = h0;
        *(__nv_bfloat162*)(g_a_lo + (size_t)r0 * DIM + d) = l0b;
        *(__nv_bfloat162*)(g_a_hi + (size_t)r1 * DIM + d) = h1;
        *(__nv_bfloat162*)(g_a_lo + (size_t)r1 * DIM + d) = l1b;
    }
}

// ------------------------------------------------------------------
// Launch
// ------------------------------------------------------------------
extern "C" void kernel_launch(void* const* d_in, const int* in_sizes, int n_in,
                              void* d_out, int out_size)
{
    const float* x  = (const float*)d_in[0];
    const float* Wq = (const float*)d_in[1];
    const float* bq = (const float*)d_in[2];
    const float* Wk = (const float*)d_in[3];
    const float* bk = (const float*)d_in[4];
    const float* Wv = (const float*)d_in[5];
    const float* bv = (const float*)d_in[6];
    const float* Wo = (const float*)d_in[7];
    const float* bo = (const float*)d_in[8];
    float* out = (float*)d_out;

    __nv_bfloat16 *a_hi, *a_lo, *wt_hi, *wt_lo;
    cudaGetSymbolAddress((void**)&a_hi, g_a_hi);
    cudaGetSymbolAddress((void**)&a_lo, g_a_lo);
    cudaGetSymbolAddress((void**)&wt_hi, g_wt_hi);
    cudaGetSymbolAddress((void**)&wt_lo, g_wt_lo);

    cudaFuncSetAttribute(qkv_tc, cudaFuncAttributeMaxDynamicSharedMemorySize, GEMM_SMEM);
    cudaFuncSetAttribute(out_tc, cudaFuncAttributeMaxDynamicSharedMemorySize, GEMM_SMEM);
    cudaFuncSetAttribute(attn_mma, cudaFuncAttributeMaxDynamicSharedMemorySize, ATTN_SMEM);

    const float qscale = 0.08838834764831845f;   // 1/sqrt(128)
    dim3 tblk(32, 8);
    dim3 tgrd(DIM / 32, DIM / 32);

    // 1) operand conversions
    convert_split<<<SEQ * DIM / 1024, 256>>>(x, a_hi, a_lo);
    convert_split_T<<<tgrd, tblk>>>(Wq, wt_hi + (size_t)0 * DIM * DIM, wt_lo + (size_t)0 * DIM * DIM, qscale);
    convert_split_T<<<tgrd, tblk>>>(Wk, wt_hi + (size_t)1 * DIM * DIM, wt_lo + (size_t)1 * DIM * DIM, 1.0f);
    convert_split_T<<<tgrd, tblk>>>(Wv, wt_hi + (size_t)2 * DIM * DIM, wt_lo + (size_t)2 * DIM * DIM, 1.0f);
    convert_split_T<<<tgrd, tblk>>>(Wo, wt_hi + (size_t)3 * DIM * DIM, wt_lo + (size_t)3 * DIM * DIM, 1.0f);

    // 2) Q/K/V projections -> bf16 hi/lo split, head-scattered
    qkv_tc<<<dim3(DIM / TNN, SEQ / TMM, 3), 256, GEMM_SMEM>>>(bq, bk, bv);

    // 3) V transpose for PV B-operand
    vt_transpose<<<dim3(DK / 32, SEQ / 32, NH), tblk>>>();

    // 4) tensor-core causal flash attention (writes split att into A operand)
    attn_mma<<<dim3(SEQ / QT, NH), 256, ATTN_SMEM>>>();

    // 5) output projection
    out_tc<<<dim3(DIM / TNN, SEQ / TMM), 256, GEMM_SMEM>>>(bo, out);
}

// round 5
// speedup vs baseline: 4.1607x; 1.5615x over previous
#include <cuda_runtime.h>
#include <cuda_fp16.h>
#include <cstdint>
#include <string.h>
#include <math.h>

// Problem constants
#define SEQ 2048
#define DIM 2048
#define NH  16
#define DK  128

// ------------------------------------------------------------------
// Scratch (device globals)
// ------------------------------------------------------------------
__device__ __half g_a_hi[SEQ * DIM];          // A operand (x, then att), exact split
__device__ __half g_a_lo[SEQ * DIM];
__device__ __half g_wt[4u * DIM * DIM];       // W^T per matrix, K-major, fp16-quantized
__device__ __half g_q_hi[NH * SEQ * DK], g_q_lo[NH * SEQ * DK];  // Q exact split
__device__ __half g_k[NH * SEQ * DK];         // K fp16-quantized
__device__ __half g_v[NH * SEQ * DK];         // V fp16-quantized
__device__ __half g_vt[NH * DK * SEQ];        // V^T [H][dk][S]

// ------------------------------------------------------------------
// Baseline-PTX helpers (sm_80-level)
// ------------------------------------------------------------------
__device__ __forceinline__ uint32_t smem_u32(const void* p) {
    uint32_t a;
    asm("{ .reg .u64 t; cvta.to.shared.u64 t, %1; cvt.u32.u64 %0, t; }" : "=r"(a) : "l"(p));
    return a;
}

#define CP_ASYNC16(sm, gp) \
    asm volatile("cp.async.cg.shared.global [%0], [%1], 16;" :: "r"(sm), "l"(gp))
#define CP_COMMIT() asm volatile("cp.async.commit_group;" ::: "memory")
#define CP_WAIT1()  asm volatile("cp.async.wait_group 1;" ::: "memory")
#define CP_WAIT0()  asm volatile("cp.async.wait_group 0;" ::: "memory")

#define LDSM_X4(r0, r1, r2, r3, addr) \
    asm volatile("ldmatrix.sync.aligned.m8n8.x4.shared.b16 {%0,%1,%2,%3}, [%4];" \
                 : "=r"(r0), "=r"(r1), "=r"(r2), "=r"(r3) : "r"(addr))

#define MMA16816(c, a, b) \
    asm volatile("mma.sync.aligned.m16n8k16.row.col.f32.f16.f16.f32 " \
                 "{%0,%1,%2,%3}, {%4,%5,%6,%7}, {%8,%9}, {%0,%1,%2,%3};" \
                 : "+f"((c)[0]), "+f"((c)[1]), "+f"((c)[2]), "+f"((c)[3]) \
                 : "r"((a)[0]), "r"((a)[1]), "r"((a)[2]), "r"((a)[3]), \
                   "r"((b)[0]), "r"((b)[1]))

__device__ __forceinline__ uint32_t h2u(__half2 v) {
    uint32_t u; memcpy(&u, &v, 4); return u;
}

// ------------------------------------------------------------------
// Conversion kernels
// ------------------------------------------------------------------
// fp32 -> exact fp16 hi/lo split
__global__ __launch_bounds__(256) void convert_split(
    const float* __restrict__ in, __half* __restrict__ hi, __half* __restrict__ lo)
{
    size_t i = ((size_t)blockIdx.x * 256 + threadIdx.x) * 4;
    float4 v = *(const float4*)(in + i);
    float vv[4] = {v.x, v.y, v.z, v.w};
    __half h[4], l[4];
#pragma unroll
    for (int j = 0; j < 4; ++j) {
        h[j] = __float2half_rn(vv[j]);
        l[j] = __float2half_rn(vv[j] - __half2float(h[j]));
    }
    *(__half2*)(hi + i)     = __halves2half2(h[0], h[1]);
    *(__half2*)(hi + i + 2) = __halves2half2(h[2], h[3]);
    *(__half2*)(lo + i)     = __halves2half2(l[0], l[1]);
    *(__half2*)(lo + i + 2) = __halves2half2(l[2], l[3]);
}

// W[K,N] -> W^T [N,K] fp16 (quantized), scale folded in
__global__ __launch_bounds__(256) void convert_cast_T(
    const float* __restrict__ W, __half* __restrict__ t, float scale)
{
    __shared__ float tile[32][33];
    int n0 = blockIdx.x * 32, k0 = blockIdx.y * 32;
    int tx = threadIdx.x, ty = threadIdx.y;   // (32, 8)
#pragma unroll
    for (int tt = 0; tt < 4; ++tt)
        tile[ty + 8 * tt][tx] = W[(size_t)(k0 + ty + 8 * tt) * DIM + n0 + tx] * scale;
    __syncthreads();
#pragma unroll
    for (int tt = 0; tt < 4; ++tt) {
        int r = ty + 8 * tt;
        t[(size_t)(n0 + r) * DIM + k0 + tx] = __float2half_rn(tile[tx][r]);
    }
}

// V [H][S][dk] -> V^T [H][dk][S]
__global__ __launch_bounds__(256) void vt_transpose()
{
    __shared__ __half th[32][33];
    int d0 = blockIdx.x * 32, s0 = blockIdx.y * 32, h = blockIdx.z;
    int tx = threadIdx.x, ty = threadIdx.y;   // (32, 8)
    const __half* vh = g_v + (size_t)h * SEQ * DK;
#pragma unroll
    for (int t = 0; t < 4; ++t)
        th[ty + 8 * t][tx] = vh[(size_t)(s0 + ty + 8 * t) * DK + d0 + tx];
    __syncthreads();
    __half* oh = g_vt + (size_t)h * DK * SEQ;
#pragma unroll
    for (int t = 0; t < 4; ++t) {
        int d = d0 + ty + 8 * t;
        oh[(size_t)d * SEQ + s0 + tx] = th[tx][ty + 8 * t];
    }
}

// ------------------------------------------------------------------
// mma.sync 2-term fp16 GEMM: out = A @ B^T + bias
// A exact (hi+lo), B fp16-quantized (hi only).
// CTA 128x128, KC=64, cp.async double buffer, 2 CTAs/SM.
// ------------------------------------------------------------------
#define TMM 128
#define TNN 128
#define KC 64
#define NCHUNK (DIM / KC)
#define LSTRIDE 144
#define TILE_B (128 * LSTRIDE)      // 18432
#define OFF_AHI 0
#define OFF_ALO (1 * TILE_B)
#define OFF_BHI (2 * TILE_B)
#define STAGE_B (3 * TILE_B)        // 55296
#define GEMM_SMEM (2 * STAGE_B)     // 110592

__device__ __forceinline__ void load_chunk(
    uint32_t sbase, const __half* __restrict__ Ahi, const __half* __restrict__ Alo,
    const __half* __restrict__ Bhi, int row0, int col0, int k0, int tid)
{
    const int col16 = tid & 7;
    const int rb    = tid >> 3;
    const int kg    = k0 + col16 * 8;
#pragma unroll
    for (int t = 0; t < 4; ++t) {
        int r = rb + t * 32;
        uint32_t so = r * LSTRIDE + col16 * 16;
        size_t ga = (size_t)(row0 + r) * DIM + kg;
        size_t gb = (size_t)(col0 + r) * DIM + kg;
        CP_ASYNC16(sbase + OFF_AHI + so, Ahi + ga);
        CP_ASYNC16(sbase + OFF_ALO + so, Alo + ga);
        CP_ASYNC16(sbase + OFF_BHI + so, Bhi + gb);
    }
}

// mode 0: fp32 [S][DIM]; mode 1: hi+lo fp16 scatter [H][S][DK]; mode 2: hi-only scatter
__device__ __forceinline__ void gemm_tc_body(
    const __half* __restrict__ Ahi, const __half* __restrict__ Alo,
    const __half* __restrict__ Bhi,
    const float* __restrict__ bias, float bscale,
    float* __restrict__ outp, __half* __restrict__ ohi, __half* __restrict__ olo,
    int mode)
{
    extern __shared__ char smg[];
    const int tid  = threadIdx.x;
    const int wid  = tid >> 5;
    const int lane = tid & 31;
    const int row0 = blockIdx.y * TMM;
    const int col0 = blockIdx.x * TNN;
    const int wm   = (wid & 3) * 32;
    const int wn   = (wid >> 2) * 64;
    const uint32_t sb = smem_u32(smg);

    float c[2][8][4];
#pragma unroll
    for (int mt = 0; mt < 2; ++mt)
#pragma unroll
        for (int nt = 0; nt < 8; ++nt)
#pragma unroll
            for (int j = 0; j < 4; ++j) c[mt][nt][j] = 0.0f;

    const uint32_t a_off = (wm + (lane & 15)) * LSTRIDE + (lane >> 4) * 16;
    const uint32_t b_row = wn + (lane & 7) + ((lane >> 4) & 1) * 8;
    const uint32_t b_off = b_row * LSTRIDE + ((lane >> 3) & 1) * 16;

    load_chunk(sb, Ahi, Alo, Bhi, row0, col0, 0, tid);
    CP_COMMIT();

    for (int ch = 0; ch < NCHUNK; ++ch) {
        const uint32_t stage = sb + (ch & 1) * STAGE_B;
        if (ch + 1 < NCHUNK) {
            load_chunk(sb + ((ch + 1) & 1) * STAGE_B, Ahi, Alo, Bhi,
                       row0, col0, (ch + 1) * KC, tid);
            CP_COMMIT();
            CP_WAIT1();
        } else {
            CP_WAIT0();
        }
        __syncthreads();

#pragma unroll
        for (int ks = 0; ks < 4; ++ks) {
            const uint32_t kb = ks * 32;
            uint32_t ahi[2][4], alo[2][4];
#pragma unroll
            for (int mt = 0; mt < 2; ++mt) {
                uint32_t ad = stage + (uint32_t)(mt * 16 * LSTRIDE) + a_off + kb;
                LDSM_X4(ahi[mt][0], ahi[mt][1], ahi[mt][2], ahi[mt][3], ad + OFF_AHI);
                LDSM_X4(alo[mt][0], alo[mt][1], alo[mt][2], alo[mt][3], ad + OFF_ALO);
            }
            uint32_t bhi[8][2];
#pragma unroll
            for (int q = 0; q < 4; ++q) {
                uint32_t bd = stage + (uint32_t)(q * 16 * LSTRIDE) + b_off + kb;
                LDSM_X4(bhi[2 * q][0], bhi[2 * q][1], bhi[2 * q + 1][0], bhi[2 * q + 1][1],
                        bd + OFF_BHI);
            }
#pragma unroll
            for (int mt = 0; mt < 2; ++mt)
#pragma unroll
                for (int nt = 0; nt < 8; ++nt) {
                    MMA16816(c[mt][nt], ahi[mt], bhi[nt]);
                    MMA16816(c[mt][nt], alo[mt], bhi[nt]);
                }
        }
        __syncthreads();
    }

#pragma unroll
    for (int mt = 0; mt < 2; ++mt) {
#pragma unroll
        for (int nt = 0; nt < 8; ++nt) {
            int cg = col0 + wn + nt * 8 + (lane & 3) * 2;
            float b0 = bias[cg] * bscale;
            float b1 = bias[cg + 1] * bscale;
            int r0 = row0 + wm + mt * 16 + (lane >> 2);
#pragma unroll
            for (int hh = 0; hh < 2; ++hh) {
                int r = r0 + hh * 8;
                float v0 = c[mt][nt][2 * hh + 0] + b0;
                float v1 = c[mt][nt][2 * hh + 1] + b1;
                if (mode == 0) {
                    float* ob = outp + (size_t)r * DIM + cg;
                    ob[0] = v0; ob[1] = v1;
                } else {
                    int hd = cg >> 7, d0 = cg & 127;
                    size_t base = ((size_t)hd * SEQ + r) * DK + d0;
                    __half h0 = __float2half_rn(v0);
                    __half h1 = __float2half_rn(v1);
                    *(__half2*)(ohi + base) = __halves2half2(h0, h1);
                    if (mode == 1) {
                        __half l0 = __float2half_rn(v0 - __half2float(h0));
                        __half l1 = __float2half_rn(v1 - __half2float(h1));
                        *(__half2*)(olo + base) = __halves2half2(l0, l1);
                    }
                }
            }
        }
    }
}

__global__ __launch_bounds__(256, 2) void qkv_tc(
    const float* __restrict__ bq, const float* __restrict__ bk, const float* __restrict__ bvv)
{
    int z = blockIdx.z;
    const __half* W = g_wt + (size_t)z * DIM * DIM;
    if (z == 0) {
        gemm_tc_body(g_a_hi, g_a_lo, W, bq, 0.08838834764831845f,
                     nullptr, g_q_hi, g_q_lo, 1);
    } else if (z == 1) {
        gemm_tc_body(g_a_hi, g_a_lo, W, bk, 1.0f, nullptr, g_k, nullptr, 2);
    } else {
        gemm_tc_body(g_a_hi, g_a_lo, W, bvv, 1.0f, nullptr, g_v, nullptr, 2);
    }
}

__global__ __launch_bounds__(256, 2) void out_tc(const float* __restrict__ bo, float* __restrict__ out)
{
    gemm_tc_body(g_a_hi, g_a_lo, g_wt + (size_t)3 * DIM * DIM, bo, 1.0f,
                 out, nullptr, nullptr, 0);
}

// ------------------------------------------------------------------
// mma.sync 2-term fp16 causal flash attention
// Q exact (hi+lo), K & V fp16-quantized, P exact (hi+lo in regs).
// CTA: 128 q-rows x 1 head. 8 warps x 16 rows. KV tiles of 64.
// ------------------------------------------------------------------
#define QT 128
#define KT 64
#define QSTR 272                      // 256B payload + 16B pad
#define VSTR 144                      // 128B payload + 16B pad
#define QB_HI 0
#define QB_LO (128 * QSTR)            // 34816
#define QB_TOT (2 * 128 * QSTR)       // 69632
#define SK 0                          // K: 64 rows x QSTR = 17408
#define SV (64 * QSTR)                // V^T: 128 rows x VSTR = 18432
#define STAGE_SZ (64 * QSTR + 128 * VSTR)   // 35840
#define ATTN_SMEM (QB_TOT + 2 * STAGE_SZ)   // 141312

__device__ __forceinline__ void attn_load_kv(uint32_t st, int h, int kv0, int tid)
{
    const __half* kh = g_k + ((size_t)h * SEQ + kv0) * DK;
    {
        int r = tid >> 2;
#pragma unroll
        for (int i = 0; i < 4; ++i) {
            int u = (tid & 3) * 4 + i;
            CP_ASYNC16(st + SK + r * QSTR + u * 16, kh + (size_t)r * DK + u * 8);
        }
    }
    const __half* vh = g_vt + (size_t)h * DK * SEQ + kv0;
    {
        int d = tid >> 1;
#pragma unroll
        for (int i = 0; i < 4; ++i) {
            int u = (tid & 1) * 4 + i;
            CP_ASYNC16(st + SV + d * VSTR + u * 16, vh + (size_t)d * SEQ + u * 8);
        }
    }
}

__global__ __launch_bounds__(256, 1) void attn_mma()
{
    extern __shared__ char sma[];
    const uint32_t sb = smem_u32(sma);
    const int tid  = threadIdx.x;
    const int wid  = tid >> 5;
    const int lane = tid & 31;
    const int h    = blockIdx.y;
    const int qi   = 15 - blockIdx.x;      // heavy tiles first
    const int q0   = qi * QT;
    const int ntiles = 2 * (qi + 1);

    // prologue: Q tile (hi+lo) + stage 0 KV
    {
        const __half* qh = g_q_hi + ((size_t)h * SEQ + q0) * DK;
        const __half* ql = g_q_lo + ((size_t)h * SEQ + q0) * DK;
        int r = tid >> 1;
#pragma unroll
        for (int i = 0; i < 8; ++i) {
            int u = (tid & 1) * 8 + i;
            CP_ASYNC16(sb + QB_HI + r * QSTR + u * 16, qh + (size_t)r * DK + u * 8);
            CP_ASYNC16(sb + QB_LO + r * QSTR + u * 16, ql + (size_t)r * DK + u * 8);
        }
        attn_load_kv(sb + QB_TOT, h, 0, tid);
        CP_COMMIT();
    }

    const uint32_t a_off  = (wid * 16 + (lane & 15)) * QSTR + (lane >> 4) * 16;
    const uint32_t bk_off = ((lane & 7) + ((lane >> 4) & 1) * 8) * QSTR + ((lane >> 3) & 1) * 16;
    const uint32_t bv_off = ((lane & 7) + ((lane >> 4) & 1) * 8) * VSTR + ((lane >> 3) & 1) * 16;

    const int row0_abs = q0 + wid * 16 + (lane >> 2);
    const int rowmax   = q0 + wid * 16 + 15;

    float o[16][4];
#pragma unroll
    for (int nt = 0; nt < 16; ++nt)
#pragma unroll
        for (int j = 0; j < 4; ++j) o[nt][j] = 0.0f;
    float m0 = -1e4f, m1 = -1e4f, l0 = 0.0f, l1 = 0.0f;

    for (int jt = 0; jt < ntiles; ++jt) {
        if (jt + 1 < ntiles) {
            attn_load_kv(sb + QB_TOT + ((jt + 1) & 1) * STAGE_SZ, h, (jt + 1) * KT, tid);
            CP_COMMIT();
            CP_WAIT1();
        } else {
            CP_WAIT0();
        }
        __syncthreads();

        const int kv0 = jt * KT;
        if (kv0 <= rowmax) {
            const uint32_t st = sb + QB_TOT + (jt & 1) * STAGE_SZ;

            // ---- S = Q K^T (qh·kh + ql·kh) ----
            float s[8][4];
#pragma unroll
            for (int nt = 0; nt < 8; ++nt)
#pragma unroll
                for (int j = 0; j < 4; ++j) s[nt][j] = 0.0f;

#pragma unroll
            for (int ks = 0; ks < 8; ++ks) {
                uint32_t ah[4], al[4];
                LDSM_X4(ah[0], ah[1], ah[2], ah[3], sb + QB_HI + a_off + ks * 32);
                LDSM_X4(al[0], al[1], al[2], al[3], sb + QB_LO + a_off + ks * 32);
                uint32_t bh[8][2];
#pragma unroll
                for (int q = 0; q < 4; ++q) {
                    uint32_t ba = st + SK + bk_off + q * (16 * QSTR) + ks * 32;
                    LDSM_X4(bh[2 * q][0], bh[2 * q][1], bh[2 * q + 1][0], bh[2 * q + 1][1], ba);
                }
#pragma unroll
                for (int nt = 0; nt < 8; ++nt) MMA16816(s[nt], ah, bh[nt]);
#pragma unroll
                for (int nt = 0; nt < 8; ++nt) MMA16816(s[nt], al, bh[nt]);
            }

            // ---- causal mask ----
            if (kv0 + KT - 1 > q0 + wid * 16) {
#pragma unroll
                for (int nt = 0; nt < 8; ++nt) {
                    int cb = kv0 + nt * 8 + (lane & 3) * 2;
#pragma unroll
                    for (int j = 0; j < 4; ++j) {
                        int col = cb + (j & 1);
                        int row = row0_abs + (j >> 1) * 8;
                        if (col > row) s[nt][j] = -1e30f;
                    }
                }
            }

            // ---- online softmax ----
            float tm0 = -1e30f, tm1 = -1e30f;
#pragma unroll
            for (int nt = 0; nt < 8; ++nt) {
                tm0 = fmaxf(tm0, fmaxf(s[nt][0], s[nt][1]));
                tm1 = fmaxf(tm1, fmaxf(s[nt][2], s[nt][3]));
            }
            tm0 = fmaxf(tm0, __shfl_xor_sync(0xffffffffu, tm0, 1));
            tm0 = fmaxf(tm0, __shfl_xor_sync(0xffffffffu, tm0, 2));
            tm1 = fmaxf(tm1, __shfl_xor_sync(0xffffffffu, tm1, 1));
            tm1 = fmaxf(tm1, __shfl_xor_sync(0xffffffffu, tm1, 2));
            float mn0 = fmaxf(fmaxf(m0, tm0), -1e4f);
            float mn1 = fmaxf(fmaxf(m1, tm1), -1e4f);
            float al0 = __expf(m0 - mn0), al1 = __expf(m1 - mn1);
            m0 = mn0; m1 = mn1;
            float ls0 = 0.0f, ls1 = 0.0f;
#pragma unroll
            for (int nt = 0; nt < 8; ++nt) {
                s[nt][0] = __expf(s[nt][0] - mn0);
                s[nt][1] = __expf(s[nt][1] - mn0);
                s[nt][2] = __expf(s[nt][2] - mn1);
                s[nt][3] = __expf(s[nt][3] - mn1);
                ls0 += s[nt][0] + s[nt][1];
                ls1 += s[nt][2] + s[nt][3];
            }
            l0 = l0 * al0 + ls0;
            l1 = l1 * al1 + ls1;
#pragma unroll
            for (int nt = 0; nt < 16; ++nt) {
                o[nt][0] *= al0; o[nt][1] *= al0;
                o[nt][2] *= al1; o[nt][3] *= al1;
            }

            // ---- pack P into PV A-frags (exact hi+lo) ----
            uint32_t aph[4][4], apl[4][4];
#pragma unroll
            for (int pr = 0; pr < 4; ++pr) {
#pragma unroll
                for (int half = 0; half < 2; ++half) {
                    int nt = 2 * pr + half;
                    __half h0 = __float2half_rn(s[nt][0]);
                    __half h1 = __float2half_rn(s[nt][1]);
                    __half h2 = __float2half_rn(s[nt][2]);
                    __half h3 = __float2half_rn(s[nt][3]);
                    __half e0 = __float2half_rn(s[nt][0] - __half2float(h0));
                    __half e1 = __float2half_rn(s[nt][1] - __half2float(h1));
                    __half e2 = __float2half_rn(s[nt][2] - __half2float(h2));
                    __half e3 = __float2half_rn(s[nt][3] - __half2float(h3));
                    aph[pr][2 * half + 0] = h2u(__halves2half2(h0, h1));
                    aph[pr][2 * half + 1] = h2u(__halves2half2(h2, h3));
                    apl[pr][2 * half + 0] = h2u(__halves2half2(e0, e1));
                    apl[pr][2 * half + 1] = h2u(__halves2half2(e2, e3));
                }
            }

            // ---- O += P V (ph·vh + pl·vh) ----
#pragma unroll
            for (int kp = 0; kp < 4; ++kp) {
#pragma unroll
                for (int half = 0; half < 2; ++half) {
                    uint32_t vh[8][2];
#pragma unroll
                    for (int q = 0; q < 4; ++q) {
                        uint32_t ba = st + SV + bv_off + (half * 4 + q) * (16 * VSTR) + kp * 32;
                        LDSM_X4(vh[2 * q][0], vh[2 * q][1], vh[2 * q + 1][0], vh[2 * q + 1][1], ba);
                    }
#pragma unroll
                    for (int nt = 0; nt < 8; ++nt) {
                        int on = half * 8 + nt;
                        MMA16816(o[on], aph[kp], vh[nt]);
                        MMA16816(o[on], apl[kp], vh[nt]);
                    }
                }
            }
        }
        __syncthreads();
    }

    // ---- epilogue: normalize, exact split, write att into A operand ----
    l0 += __shfl_xor_sync(0xffffffffu, l0, 1);
    l0 += __shfl_xor_sync(0xffffffffu, l0, 2);
    l1 += __shfl_xor_sync(0xffffffffu, l1, 1);
    l1 += __shfl_xor_sync(0xffffffffu, l1, 2);
    float inv0 = 1.0f / l0, inv1 = 1.0f / l1;

    const int r0 = row0_abs;
    const int r1 = row0_abs + 8;
#pragma unroll
    for (int nt = 0; nt < 16; ++nt) {
        int d = h * DK + nt * 8 + (lane & 3) * 2;
        float v00 = o[nt][0] * inv0, v01 = o[nt][1] * inv0;
        float v10 = o[nt][2] * inv1, v11 = o[nt][3] * inv1;
        __half h00 = __float2half_rn(v00), h01 = __float2half_rn(v01);
        __half h10 = __float2half_rn(v10), h11 = __float2half_rn(v11);
        *(__half2*)(g_a_hi + (size_t)r0 * DIM + d) = __halves2half2(h00, h01);
        *(__half2*)(g_a_lo + (size_t)r0 * DIM + d) =
            __halves2half2(__float2half_rn(v00 - __half2float(h00)),
                           __float2half_rn(v01 - __half2float(h01)));
        *(__half2*)(g_a_hi + (size_t)r1 * DIM + d) = __halves2half2(h10, h11);
        *(__half2*)(g_a_lo + (size_t)r1 * DIM + d) =
            __halves2half2(__float2half_rn(v10 - __half2float(h10)),
                           __float2half_rn(v11 - __half2float(h11)));
    }
}

// ------------------------------------------------------------------
// Launch
// ------------------------------------------------------------------
extern "C" void kernel_launch(void* const* d_in, const int* in_sizes, int n_in,
                              void* d_out, int out_size)
{
    const float* x  = (const float*)d_in[0];
    const float* Wq = (const float*)d_in[1];
    const float* bq = (const float*)d_in[2];
    const float* Wk = (const float*)d_in[3];
    const float* bk = (const float*)d_in[4];
    const float* Wv = (const float*)d_in[5];
    const float* bv = (const float*)d_in[6];
    const float* Wo = (const float*)d_in[7];
    const float* bo = (const float*)d_in[8];
    float* out = (float*)d_out;

    __half *a_hi, *a_lo, *wt;
    cudaGetSymbolAddress((void**)&a_hi, g_a_hi);
    cudaGetSymbolAddress((void**)&a_lo, g_a_lo);
    cudaGetSymbolAddress((void**)&wt, g_wt);

    cudaFuncSetAttribute(qkv_tc, cudaFuncAttributeMaxDynamicSharedMemorySize, GEMM_SMEM);
    cudaFuncSetAttribute(out_tc, cudaFuncAttributeMaxDynamicSharedMemorySize, GEMM_SMEM);
    cudaFuncSetAttribute(attn_mma, cudaFuncAttributeMaxDynamicSharedMemorySize, ATTN_SMEM);

    const float qscale = 0.08838834764831845f;   // 1/sqrt(128)
    dim3 tblk(32, 8);
    dim3 tgrd(DIM / 32, DIM / 32);

    // 1) operand conversions
    convert_split<<<SEQ * DIM / 1024, 256>>>(x, a_hi, a_lo);
    convert_cast_T<<<tgrd, tblk>>>(Wq, wt + (size_t)0 * DIM * DIM, qscale);
    convert_cast_T<<<tgrd, tblk>>>(Wk, wt + (size_t)1 * DIM * DIM, 1.0f);
    convert_cast_T<<<tgrd, tblk>>>(Wv, wt + (size_t)2 * DIM * DIM, 1.0f);
    convert_cast_T<<<tgrd, tblk>>>(Wo, wt + (size_t)3 * DIM * DIM, 1.0f);

    // 2) Q/K/V projections (Q exact split; K,V fp16)
    qkv_tc<<<dim3(DIM / TNN, SEQ / TMM, 3), 256, GEMM_SMEM>>>(bq, bk, bv);

    // 3) V transpose for PV B-operand
    vt_transpose<<<dim3(DK / 32, SEQ / 32, NH), tblk>>>();

    // 4) tensor-core causal flash attention
    attn_mma<<<dim3(SEQ / QT, NH), 256, ATTN_SMEM>>>();

    // 5) output projection
    out_tc<<<dim3(DIM / TNN, SEQ / TMM), 256, GEMM_SMEM>>>(bo, out);
}

// round 6
// speedup vs baseline: 4.2445x; 1.0201x over previous
#include <cuda_runtime.h>
#include <cuda_fp16.h>
#include <cstdint>
#include <string.h>
#include <math.h>

// Problem constants
#define SEQ 2048
#define DIM 2048
#define NH  16
#define DK  128

// ------------------------------------------------------------------
// Scratch (device globals)
// ------------------------------------------------------------------
__device__ __half g_a_hi[SEQ * DIM];          // A operand (x, then att), exact split
__device__ __half g_a_lo[SEQ * DIM];
__device__ __half g_wt[4u * DIM * DIM];       // W^T per matrix, K-major, fp16-quantized
__device__ __half g_q_hi[NH * SEQ * DK], g_q_lo[NH * SEQ * DK];  // Q exact split
__device__ __half g_k[NH * SEQ * DK];         // K fp16-quantized
__device__ __half g_v[NH * SEQ * DK];         // V fp16-quantized (row-major, trans at ldmatrix)

// ------------------------------------------------------------------
// Baseline-PTX helpers (sm_80-level)
// ------------------------------------------------------------------
__device__ __forceinline__ uint32_t smem_u32(const void* p) {
    uint32_t a;
    asm("{ .reg .u64 t; cvta.to.shared.u64 t, %1; cvt.u32.u64 %0, t; }" : "=r"(a) : "l"(p));
    return a;
}

#define CP_ASYNC16(sm, gp) \
    asm volatile("cp.async.cg.shared.global [%0], [%1], 16;" :: "r"(sm), "l"(gp))
#define CP_COMMIT() asm volatile("cp.async.commit_group;" ::: "memory")
#define CP_WAIT1()  asm volatile("cp.async.wait_group 1;" ::: "memory")
#define CP_WAIT0()  asm volatile("cp.async.wait_group 0;" ::: "memory")

#define LDSM_X4(r0, r1, r2, r3, addr) \
    asm volatile("ldmatrix.sync.aligned.m8n8.x4.shared.b16 {%0,%1,%2,%3}, [%4];" \
                 : "=r"(r0), "=r"(r1), "=r"(r2), "=r"(r3) : "r"(addr))

#define LDSM_X4_T(r0, r1, r2, r3, addr) \
    asm volatile("ldmatrix.sync.aligned.m8n8.x4.trans.shared.b16 {%0,%1,%2,%3}, [%4];" \
                 : "=r"(r0), "=r"(r1), "=r"(r2), "=r"(r3) : "r"(addr))

#define MMA16816(c, a, b) \
    asm volatile("mma.sync.aligned.m16n8k16.row.col.f32.f16.f16.f32 " \
                 "{%0,%1,%2,%3}, {%4,%5,%6,%7}, {%8,%9}, {%0,%1,%2,%3};" \
                 : "+f"((c)[0]), "+f"((c)[1]), "+f"((c)[2]), "+f"((c)[3]) \
                 : "r"((a)[0]), "r"((a)[1]), "r"((a)[2]), "r"((a)[3]), \
                   "r"((b)[0]), "r"((b)[1]))

__device__ __forceinline__ uint32_t h2u(__half2 v) {
    uint32_t u; memcpy(&u, &v, 4); return u;
}

// ------------------------------------------------------------------
// Conversion kernels
// ------------------------------------------------------------------
// fp32 -> exact fp16 hi/lo split
__global__ __launch_bounds__(256) void convert_split(
    const float* __restrict__ in, __half* __restrict__ hi, __half* __restrict__ lo)
{
    size_t i = ((size_t)blockIdx.x * 256 + threadIdx.x) * 4;
    float4 v = *(const float4*)(in + i);
    float vv[4] = {v.x, v.y, v.z, v.w};
    __half h[4], l[4];
#pragma unroll
    for (int j = 0; j < 4; ++j) {
        h[j] = __float2half_rn(vv[j]);
        l[j] = __float2half_rn(vv[j] - __half2float(h[j]));
    }
    *(__half2*)(hi + i)     = __halves2half2(h[0], h[1]);
    *(__half2*)(hi + i + 2) = __halves2half2(h[2], h[3]);
    *(__half2*)(lo + i)     = __halves2half2(l[0], l[1]);
    *(__half2*)(lo + i + 2) = __halves2half2(l[2], l[3]);
}

// All four W[K,N] -> W^T [N,K] fp16 (quantized), one launch; Wq scale folded in
__global__ __launch_bounds__(256) void convert_w_all(
    const float* __restrict__ Wq, const float* __restrict__ Wk,
    const float* __restrict__ Wv, const float* __restrict__ Wo)
{
    __shared__ float tile[32][33];
    int z = blockIdx.z;
    const float* W = (z == 0) ? Wq : (z == 1) ? Wk : (z == 2) ? Wv : Wo;
    float scale = (z == 0) ? 0.08838834764831845f : 1.0f;
    __half* t = g_wt + (size_t)z * DIM * DIM;

    int n0 = blockIdx.x * 32, k0 = blockIdx.y * 32;
    int tx = threadIdx.x, ty = threadIdx.y;   // (32, 8)
#pragma unroll
    for (int tt = 0; tt < 4; ++tt)
        tile[ty + 8 * tt][tx] = W[(size_t)(k0 + ty + 8 * tt) * DIM + n0 + tx] * scale;
    __syncthreads();
#pragma unroll
    for (int tt = 0; tt < 4; ++tt) {
        int r = ty + 8 * tt;
        t[(size_t)(n0 + r) * DIM + k0 + tx] = __float2half_rn(tile[tx][r]);
    }
}

// ------------------------------------------------------------------
// mma.sync 2-term fp16 GEMM: out = A @ B^T + bias
// A exact (hi+lo), B fp16-quantized (hi only).
// CTA 128x128, KC=64, cp.async double buffer, 2 CTAs/SM.
// ------------------------------------------------------------------
#define TMM 128
#define TNN 128
#define KC 64
#define NCHUNK (DIM / KC)
#define LSTRIDE 144
#define TILE_B (128 * LSTRIDE)      // 18432
#define OFF_AHI 0
#define OFF_ALO (1 * TILE_B)
#define OFF_BHI (2 * TILE_B)
#define STAGE_B (3 * TILE_B)        // 55296
#define GEMM_SMEM (2 * STAGE_B)     // 110592

__device__ __forceinline__ void load_chunk(
    uint32_t sbase, const __half* __restrict__ Ahi, const __half* __restrict__ Alo,
    const __half* __restrict__ Bhi, int row0, int col0, int k0, int tid)
{
    const int col16 = tid & 7;
    const int rb    = tid >> 3;
    const int kg    = k0 + col16 * 8;
#pragma unroll
    for (int t = 0; t < 4; ++t) {
        int r = rb + t * 32;
        uint32_t so = r * LSTRIDE + col16 * 16;
        size_t ga = (size_t)(row0 + r) * DIM + kg;
        size_t gb = (size_t)(col0 + r) * DIM + kg;
        CP_ASYNC16(sbase + OFF_AHI + so, Ahi + ga);
        CP_ASYNC16(sbase + OFF_ALO + so, Alo + ga);
        CP_ASYNC16(sbase + OFF_BHI + so, Bhi + gb);
    }
}

// mode 0: fp32 [S][DIM]; mode 1: hi+lo fp16 scatter [H][S][DK]; mode 2: hi-only scatter
__device__ __forceinline__ void gemm_tc_body(
    const __half* __restrict__ Ahi, const __half* __restrict__ Alo,
    const __half* __restrict__ Bhi,
    const float* __restrict__ bias, float bscale,
    float* __restrict__ outp, __half* __restrict__ ohi, __half* __restrict__ olo,
    int mode)
{
    extern __shared__ char smg[];
    const int tid  = threadIdx.x;
    const int wid  = tid >> 5;
    const int lane = tid & 31;
    const int row0 = blockIdx.y * TMM;
    const int col0 = blockIdx.x * TNN;
    const int wm   = (wid & 3) * 32;
    const int wn   = (wid >> 2) * 64;
    const uint32_t sb = smem_u32(smg);

    float c[2][8][4];
#pragma unroll
    for (int mt = 0; mt < 2; ++mt)
#pragma unroll
        for (int nt = 0; nt < 8; ++nt)
#pragma unroll
            for (int j = 0; j < 4; ++j) c[mt][nt][j] = 0.0f;

    const uint32_t a_off = (wm + (lane & 15)) * LSTRIDE + (lane >> 4) * 16;
    const uint32_t b_row = wn + (lane & 7) + ((lane >> 4) & 1) * 8;
    const uint32_t b_off = b_row * LSTRIDE + ((lane >> 3) & 1) * 16;

    load_chunk(sb, Ahi, Alo, Bhi, row0, col0, 0, tid);
    CP_COMMIT();

    for (int ch = 0; ch < NCHUNK; ++ch) {
        const uint32_t stage = sb + (ch & 1) * STAGE_B;
        if (ch + 1 < NCHUNK) {
            load_chunk(sb + ((ch + 1) & 1) * STAGE_B, Ahi, Alo, Bhi,
                       row0, col0, (ch + 1) * KC, tid);
            CP_COMMIT();
            CP_WAIT1();
        } else {
            CP_WAIT0();
        }
        __syncthreads();

#pragma unroll
        for (int ks = 0; ks < 4; ++ks) {
            const uint32_t kb = ks * 32;
            uint32_t ahi[2][4], alo[2][4];
#pragma unroll
            for (int mt = 0; mt < 2; ++mt) {
                uint32_t ad = stage + (uint32_t)(mt * 16 * LSTRIDE) + a_off + kb;
                LDSM_X4(ahi[mt][0], ahi[mt][1], ahi[mt][2], ahi[mt][3], ad + OFF_AHI);
                LDSM_X4(alo[mt][0], alo[mt][1], alo[mt][2], alo[mt][3], ad + OFF_ALO);
            }
            uint32_t bhi[8][2];
#pragma unroll
            for (int q = 0; q < 4; ++q) {
                uint32_t bd = stage + (uint32_t)(q * 16 * LSTRIDE) + b_off + kb;
                LDSM_X4(bhi[2 * q][0], bhi[2 * q][1], bhi[2 * q + 1][0], bhi[2 * q + 1][1],
                        bd + OFF_BHI);
            }
#pragma unroll
            for (int mt = 0; mt < 2; ++mt)
#pragma unroll
                for (int nt = 0; nt < 8; ++nt) {
                    MMA16816(c[mt][nt], ahi[mt], bhi[nt]);
                    MMA16816(c[mt][nt], alo[mt], bhi[nt]);
                }
        }
        __syncthreads();
    }

#pragma unroll
    for (int mt = 0; mt < 2; ++mt) {
#pragma unroll
        for (int nt = 0; nt < 8; ++nt) {
            int cg = col0 + wn + nt * 8 + (lane & 3) * 2;
            float b0 = bias[cg] * bscale;
            float b1 = bias[cg + 1] * bscale;
            int r0 = row0 + wm + mt * 16 + (lane >> 2);
#pragma unroll
            for (int hh = 0; hh < 2; ++hh) {
                int r = r0 + hh * 8;
                float v0 = c[mt][nt][2 * hh + 0] + b0;
                float v1 = c[mt][nt][2 * hh + 1] + b1;
                if (mode == 0) {
                    float* ob = outp + (size_t)r * DIM + cg;
                    ob[0] = v0; ob[1] = v1;
                } else {
                    int hd = cg >> 7, d0 = cg & 127;
                    size_t base = ((size_t)hd * SEQ + r) * DK + d0;
                    __half h0 = __float2half_rn(v0);
                    __half h1 = __float2half_rn(v1);
                    *(__half2*)(ohi + base) = __halves2half2(h0, h1);
                    if (mode == 1) {
                        __half l0 = __float2half_rn(v0 - __half2float(h0));
                        __half l1 = __float2half_rn(v1 - __half2float(h1));
                        *(__half2*)(olo + base) = __halves2half2(l0, l1);
                    }
                }
            }
        }
    }
}

__global__ __launch_bounds__(256, 2) void qkv_tc(
    const float* __restrict__ bq, const float* __restrict__ bk, const float* __restrict__ bvv)
{
    int z = blockIdx.z;
    const __half* W = g_wt + (size_t)z * DIM * DIM;
    if (z == 0) {
        gemm_tc_body(g_a_hi, g_a_lo, W, bq, 0.08838834764831845f,
                     nullptr, g_q_hi, g_q_lo, 1);
    } else if (z == 1) {
        gemm_tc_body(g_a_hi, g_a_lo, W, bk, 1.0f, nullptr, g_k, nullptr, 2);
    } else {
        gemm_tc_body(g_a_hi, g_a_lo, W, bvv, 1.0f, nullptr, g_v, nullptr, 2);
    }
}

__global__ __launch_bounds__(256, 2) void out_tc(const float* __restrict__ bo, float* __restrict__ out)
{
    gemm_tc_body(g_a_hi, g_a_lo, g_wt + (size_t)3 * DIM * DIM, bo, 1.0f,
                 out, nullptr, nullptr, 0);
}

// ------------------------------------------------------------------
// mma.sync 2-term fp16 causal flash attention
// Q exact (hi+lo), K & V fp16-quantized. V row-major, transposed via
// ldmatrix.x4.trans at fragment-load time (no separate V^T buffer).
// CTA: 128 q-rows x 1 head. 8 warps x 16 rows. KV tiles of 64.
// ------------------------------------------------------------------
#define QT 128
#define KT 64
#define QSTR 272                      // 256B payload + 16B pad
#define QB_HI 0
#define QB_LO (128 * QSTR)            // 34816
#define QB_TOT (2 * 128 * QSTR)       // 69632
#define SK 0                          // K: 64 rows x QSTR = 17408
#define SV (64 * QSTR)                // V: 64 rows x QSTR = 17408
#define STAGE_SZ (2 * 64 * QSTR)      // 34816
#define ATTN_SMEM (QB_TOT + 2 * STAGE_SZ)   // 139264

__device__ __forceinline__ void attn_load_kv(uint32_t st, int h, int kv0, int tid)
{
    const __half* kh = g_k + ((size_t)h * SEQ + kv0) * DK;
    const __half* vh = g_v + ((size_t)h * SEQ + kv0) * DK;
    int r = tid >> 2;
#pragma unroll
    for (int i = 0; i < 4; ++i) {
        int u = (tid & 3) * 4 + i;
        CP_ASYNC16(st + SK + r * QSTR + u * 16, kh + (size_t)r * DK + u * 8);
        CP_ASYNC16(st + SV + r * QSTR + u * 16, vh + (size_t)r * DK + u * 8);
    }
}

__global__ __launch_bounds__(256, 1) void attn_mma()
{
    extern __shared__ char sma[];
    const uint32_t sb = smem_u32(sma);
    const int tid  = threadIdx.x;
    const int wid  = tid >> 5;
    const int lane = tid & 31;
    const int h    = blockIdx.y;
    const int qi   = 15 - blockIdx.x;      // heavy tiles first
    const int q0   = qi * QT;
    const int ntiles = 2 * (qi + 1);

    // prologue: Q tile (hi+lo) + stage 0 KV
    {
        const __half* qh = g_q_hi + ((size_t)h * SEQ + q0) * DK;
        const __half* ql = g_q_lo + ((size_t)h * SEQ + q0) * DK;
        int r = tid >> 1;
#pragma unroll
        for (int i = 0; i < 8; ++i) {
            int u = (tid & 1) * 8 + i;
            CP_ASYNC16(sb + QB_HI + r * QSTR + u * 16, qh + (size_t)r * DK + u * 8);
            CP_ASYNC16(sb + QB_LO + r * QSTR + u * 16, ql + (size_t)r * DK + u * 8);
        }
        attn_load_kv(sb + QB_TOT, h, 0, tid);
        CP_COMMIT();
    }

    // per-lane fragment address components
    const uint32_t a_off  = (wid * 16 + (lane & 15)) * QSTR + (lane >> 4) * 16;
    const uint32_t bk_off = ((lane & 7) + ((lane >> 4) & 1) * 8) * QSTR + ((lane >> 3) & 1) * 16;
    // V via ldmatrix.trans: tiles (k0-7,d0)(k8-15,d0)(k0-7,d1)(k8-15,d1)
    const uint32_t bv_off = ((lane & 7) + ((lane >> 3) & 1) * 8) * QSTR + ((lane >> 4) & 1) * 16;

    const int row0_abs = q0 + wid * 16 + (lane >> 2);
    const int rowmax   = q0 + wid * 16 + 15;

    float o[16][4];
#pragma unroll
    for (int nt = 0; nt < 16; ++nt)
#pragma unroll
        for (int j = 0; j < 4; ++j) o[nt][j] = 0.0f;
    float m0 = -1e4f, m1 = -1e4f, l0 = 0.0f, l1 = 0.0f;

    for (int jt = 0; jt < ntiles; ++jt) {
        if (jt + 1 < ntiles) {
            attn_load_kv(sb + QB_TOT + ((jt + 1) & 1) * STAGE_SZ, h, (jt + 1) * KT, tid);
            CP_COMMIT();
            CP_WAIT1();
        } else {
            CP_WAIT0();
        }
        __syncthreads();

        const int kv0 = jt * KT;
        if (kv0 <= rowmax) {
            const uint32_t st = sb + QB_TOT + (jt & 1) * STAGE_SZ;

            // ---- S = Q K^T (qh·kh + ql·kh) ----
            float s[8][4];
#pragma unroll
            for (int nt = 0; nt < 8; ++nt)
#pragma unroll
                for (int j = 0; j < 4; ++j) s[nt][j] = 0.0f;

#pragma unroll
            for (int ks = 0; ks < 8; ++ks) {
                uint32_t ah[4], al[4];
                LDSM_X4(ah[0], ah[1], ah[2], ah[3], sb + QB_HI + a_off + ks * 32);
                LDSM_X4(al[0], al[1], al[2], al[3], sb + QB_LO + a_off + ks * 32);
                uint32_t bh[8][2];
#pragma unroll
                for (int q = 0; q < 4; ++q) {
                    uint32_t ba = st + SK + bk_off + q * (16 * QSTR) + ks * 32;
                    LDSM_X4(bh[2 * q][0], bh[2 * q][1], bh[2 * q + 1][0], bh[2 * q + 1][1], ba);
                }
#pragma unroll
                for (int nt = 0; nt < 8; ++nt) MMA16816(s[nt], ah, bh[nt]);
#pragma unroll
                for (int nt = 0; nt < 8; ++nt) MMA16816(s[nt], al, bh[nt]);
            }

            // ---- causal mask ----
            if (kv0 + KT - 1 > q0 + wid * 16) {
#pragma unroll
                for (int nt = 0; nt < 8; ++nt) {
                    int cb = kv0 + nt * 8 + (lane & 3) * 2;
#pragma unroll
                    for (int j = 0; j < 4; ++j) {
                        int col = cb + (j & 1);
                        int row = row0_abs + (j >> 1) * 8;
                        if (col > row) s[nt][j] = -1e30f;
                    }
                }
            }

            // ---- online softmax ----
            float tm0 = -1e30f, tm1 = -1e30f;
#pragma unroll
            for (int nt = 0; nt < 8; ++nt) {
                tm0 = fmaxf(tm0, fmaxf(s[nt][0], s[nt][1]));
                tm1 = fmaxf(tm1, fmaxf(s[nt][2], s[nt][3]));
            }
            tm0 = fmaxf(tm0, __shfl_xor_sync(0xffffffffu, tm0, 1));
            tm0 = fmaxf(tm0, __shfl_xor_sync(0xffffffffu, tm0, 2));
            tm1 = fmaxf(tm1, __shfl_xor_sync(0xffffffffu, tm1, 1));
            tm1 = fmaxf(tm1, __shfl_xor_sync(0xffffffffu, tm1, 2));
            float mn0 = fmaxf(fmaxf(m0, tm0), -1e4f);
            float mn1 = fmaxf(fmaxf(m1, tm1), -1e4f);
            float al0 = __expf(m0 - mn0), al1 = __expf(m1 - mn1);
            m0 = mn0; m1 = mn1;
            float ls0 = 0.0f, ls1 = 0.0f;
#pragma unroll
            for (int nt = 0; nt < 8; ++nt) {
                s[nt][0] = __expf(s[nt][0] - mn0);
                s[nt][1] = __expf(s[nt][1] - mn0);
                s[nt][2] = __expf(s[nt][2] - mn1);
                s[nt][3] = __expf(s[nt][3] - mn1);
                ls0 += s[nt][0] + s[nt][1];
                ls1 += s[nt][2] + s[nt][3];
            }
            l0 = l0 * al0 + ls0;
            l1 = l1 * al1 + ls1;
#pragma unroll
            for (int nt = 0; nt < 16; ++nt) {
                o[nt][0] *= al0; o[nt][1] *= al0;
                o[nt][2] *= al1; o[nt][3] *= al1;
            }

            // ---- pack P into PV A-frags (exact hi+lo) ----
            uint32_t aph[4][4], apl[4][4];
#pragma unroll
            for (int pr = 0; pr < 4; ++pr) {
#pragma unroll
                for (int half = 0; half < 2; ++half) {
                    int nt = 2 * pr + half;
                    __half h0 = __float2half_rn(s[nt][0]);
                    __half h1 = __float2half_rn(s[nt][1]);
                    __half h2 = __float2half_rn(s[nt][2]);
                    __half h3 = __float2half_rn(s[nt][3]);
                    __half e0 = __float2half_rn(s[nt][0] - __half2float(h0));
                    __half e1 = __float2half_rn(s[nt][1] - __half2float(h1));
                    __half e2 = __float2half_rn(s[nt][2] - __half2float(h2));
                    __half e3 = __float2half_rn(s[nt][3] - __half2float(h3));
                    aph[pr][2 * half + 0] = h2u(__halves2half2(h0, h1));
                    aph[pr][2 * half + 1] = h2u(__halves2half2(h2, h3));
                    apl[pr][2 * half + 0] = h2u(__halves2half2(e0, e1));
                    apl[pr][2 * half + 1] = h2u(__halves2half2(e2, e3));
                }
            }

            // ---- O += P V (ph·vh + pl·vh), V frags via ldmatrix.trans ----
#pragma unroll
            for (int kp = 0; kp < 4; ++kp) {
#pragma unroll
                for (int p = 0; p < 8; ++p) {
                    uint32_t r0, r1, r2, r3;
                    LDSM_X4_T(r0, r1, r2, r3,
                              st + SV + bv_off + kp * (16 * QSTR) + p * 32);
                    uint32_t b01[2] = {r0, r1};
                    uint32_t b23[2] = {r2, r3};
                    MMA16816(o[2 * p + 0], aph[kp], b01);
                    MMA16816(o[2 * p + 0], apl[kp], b01);
                    MMA16816(o[2 * p + 1], aph[kp], b23);
                    MMA16816(o[2 * p + 1], apl[kp], b23);
                }
            }
        }
        __syncthreads();
    }

    // ---- epilogue: normalize, exact split, write att into A operand ----
    l0 += __shfl_xor_sync(0xffffffffu, l0, 1);
    l0 += __shfl_xor_sync(0xffffffffu, l0, 2);
    l1 += __shfl_xor_sync(0xffffffffu, l1, 1);
    l1 += __shfl_xor_sync(0xffffffffu, l1, 2);
    float inv0 = 1.0f / l0, inv1 = 1.0f / l1;

    const int r0 = row0_abs;
    const int r1 = row0_abs + 8;
#pragma unroll
    for (int nt = 0; nt < 16; ++nt) {
        int d = h * DK + nt * 8 + (lane & 3) * 2;
        float v00 = o[nt][0] * inv0, v01 = o[nt][1] * inv0;
        float v10 = o[nt][2] * inv1, v11 = o[nt][3] * inv1;
        __half h00 = __float2half_rn(v00), h01 = __float2half_rn(v01);
        __half h10 = __float2half_rn(v10), h11 = __float2half_rn(v11);
        *(__half2*)(g_a_hi + (size_t)r0 * DIM + d) = __halves2half2(h00, h01);
        *(__half2*)(g_a_lo + (size_t)r0 * DIM + d) =
            __halves2half2(__float2half_rn(v00 - __half2float(h00)),
                           __float2half_rn(v01 - __half2float(h01)));
        *(__half2*)(g_a_hi + (size_t)r1 * DIM + d) = __halves2half2(h10, h11);
        *(__half2*)(g_a_lo + (size_t)r1 * DIM + d) =
            __halves2half2(__float2half_rn(v10 - __half2float(h10)),
                           __float2half_rn(v11 - __half2float(h11)));
    }
}

// ------------------------------------------------------------------
// Launch
// ------------------------------------------------------------------
extern "C" void kernel_launch(void* const* d_in, const int* in_sizes, int n_in,
                              void* d_out, int out_size)
{
    const float* x  = (const float*)d_in[0];
    const float* Wq = (const float*)d_in[1];
    const float* bq = (const float*)d_in[2];
    const float* Wk = (const float*)d_in[3];
    const float* bk = (const float*)d_in[4];
    const float* Wv = (const float*)d_in[5];
    const float* bv = (const float*)d_in[6];
    const float* Wo = (const float*)d_in[7];
    const float* bo = (const float*)d_in[8];
    float* out = (float*)d_out;

    __half *a_hi, *a_lo;
    cudaGetSymbolAddress((void**)&a_hi, g_a_hi);
    cudaGetSymbolAddress((void**)&a_lo, g_a_lo);

    cudaFuncSetAttribute(qkv_tc, cudaFuncAttributeMaxDynamicSharedMemorySize, GEMM_SMEM);
    cudaFuncSetAttribute(out_tc, cudaFuncAttributeMaxDynamicSharedMemorySize, GEMM_SMEM);
    cudaFuncSetAttribute(attn_mma, cudaFuncAttributeMaxDynamicSharedMemorySize, ATTN_SMEM);

    dim3 tblk(32, 8);

    // 1) operand conversions (2 launches)
    convert_split<<<SEQ * DIM / 1024, 256>>>(x, a_hi, a_lo);
    convert_w_all<<<dim3(DIM / 32, DIM / 32, 4), tblk>>>(Wq, Wk, Wv, Wo);

    // 2) Q/K/V projections (Q exact split; K,V fp16)
    qkv_tc<<<dim3(DIM / TNN, SEQ / TMM, 3), 256, GEMM_SMEM>>>(bq, bk, bv);

    // 3) tensor-core causal flash attention (V transposed via ldmatrix.trans)
    attn_mma<<<dim3(SEQ / QT, NH), 256, ATTN_SMEM>>>();

    // 4) output projection
    out_tc<<<dim3(DIM / TNN, SEQ / TMM), 256, GEMM_SMEM>>>(bo, out);
}

// round 7
// speedup vs baseline: 5.3953x; 1.2711x over previous
#include <cuda_runtime.h>
#include <cuda_fp16.h>
#include <cstdint>
#include <string.h>
#include <math.h>

// Problem constants
#define SEQ 2048
#define DIM 2048
#define NH  16
#define DK  128

// ------------------------------------------------------------------
// Scratch (device globals)
// ------------------------------------------------------------------
__device__ __half g_a_hi[SEQ * DIM];          // A operand (x, then att), exact split
__device__ __half g_a_lo[SEQ * DIM];
__device__ __half g_wt[4u * DIM * DIM];       // W^T per matrix, K-major, fp16-quantized
__device__ __half g_q[NH * SEQ * DK];         // Q fp16 (1/sqrt(dk) folded)
__device__ __half g_k[NH * SEQ * DK];         // K fp16
__device__ __half g_v[NH * SEQ * DK];         // V fp16 (row-major, trans at ldmatrix)

// ------------------------------------------------------------------
// Baseline-PTX helpers (sm_80-level)
// ------------------------------------------------------------------
__device__ __forceinline__ uint32_t smem_u32(const void* p) {
    uint32_t a;
    asm("{ .reg .u64 t; cvta.to.shared.u64 t, %1; cvt.u32.u64 %0, t; }" : "=r"(a) : "l"(p));
    return a;
}

#define CP_ASYNC16(sm, gp) \
    asm volatile("cp.async.cg.shared.global [%0], [%1], 16;" :: "r"(sm), "l"(gp))
#define CP_COMMIT() asm volatile("cp.async.commit_group;" ::: "memory")
#define CP_WAIT1()  asm volatile("cp.async.wait_group 1;" ::: "memory")
#define CP_WAIT0()  asm volatile("cp.async.wait_group 0;" ::: "memory")

#define LDSM_X4(r0, r1, r2, r3, addr) \
    asm volatile("ldmatrix.sync.aligned.m8n8.x4.shared.b16 {%0,%1,%2,%3}, [%4];" \
                 : "=r"(r0), "=r"(r1), "=r"(r2), "=r"(r3) : "r"(addr))

#define LDSM_X4_T(r0, r1, r2, r3, addr) \
    asm volatile("ldmatrix.sync.aligned.m8n8.x4.trans.shared.b16 {%0,%1,%2,%3}, [%4];" \
                 : "=r"(r0), "=r"(r1), "=r"(r2), "=r"(r3) : "r"(addr))

#define MMA16816(c, a, b) \
    asm volatile("mma.sync.aligned.m16n8k16.row.col.f32.f16.f16.f32 " \
                 "{%0,%1,%2,%3}, {%4,%5,%6,%7}, {%8,%9}, {%0,%1,%2,%3};" \
                 : "+f"((c)[0]), "+f"((c)[1]), "+f"((c)[2]), "+f"((c)[3]) \
                 : "r"((a)[0]), "r"((a)[1]), "r"((a)[2]), "r"((a)[3]), \
                   "r"((b)[0]), "r"((b)[1]))

__device__ __forceinline__ uint32_t h2u(__half2 v) {
    uint32_t u; memcpy(&u, &v, 4); return u;
}

// ------------------------------------------------------------------
// Conversion kernels
// ------------------------------------------------------------------
// fp32 -> exact fp16 hi/lo split
__global__ __launch_bounds__(256) void convert_split(
    const float* __restrict__ in, __half* __restrict__ hi, __half* __restrict__ lo)
{
    size_t i = ((size_t)blockIdx.x * 256 + threadIdx.x) * 4;
    float4 v = *(const float4*)(in + i);
    float vv[4] = {v.x, v.y, v.z, v.w};
    __half h[4], l[4];
#pragma unroll
    for (int j = 0; j < 4; ++j) {
        h[j] = __float2half_rn(vv[j]);
        l[j] = __float2half_rn(vv[j] - __half2float(h[j]));
    }
    *(__half2*)(hi + i)     = __halves2half2(h[0], h[1]);
    *(__half2*)(hi + i + 2) = __halves2half2(h[2], h[3]);
    *(__half2*)(lo + i)     = __halves2half2(l[0], l[1]);
    *(__half2*)(lo + i + 2) = __halves2half2(l[2], l[3]);
}

// All four W[K,N] -> W^T [N,K] fp16 (quantized), one launch; Wq scale folded in
__global__ __launch_bounds__(256) void convert_w_all(
    const float* __restrict__ Wq, const float* __restrict__ Wk,
    const float* __restrict__ Wv, const float* __restrict__ Wo)
{
    __shared__ float tile[32][33];
    int z = blockIdx.z;
    const float* W = (z == 0) ? Wq : (z == 1) ? Wk : (z == 2) ? Wv : Wo;
    float scale = (z == 0) ? 0.08838834764831845f : 1.0f;
    __half* t = g_wt + (size_t)z * DIM * DIM;

    int n0 = blockIdx.x * 32, k0 = blockIdx.y * 32;
    int tx = threadIdx.x, ty = threadIdx.y;   // (32, 8)
#pragma unroll
    for (int tt = 0; tt < 4; ++tt)
        tile[ty + 8 * tt][tx] = W[(size_t)(k0 + ty + 8 * tt) * DIM + n0 + tx] * scale;
    __syncthreads();
#pragma unroll
    for (int tt = 0; tt < 4; ++tt) {
        int r = ty + 8 * tt;
        t[(size_t)(n0 + r) * DIM + k0 + tx] = __float2half_rn(tile[tx][r]);
    }
}

// ------------------------------------------------------------------
// mma.sync fp16 GEMM: out = A @ B^T + bias
// USE_ALO=1: A exact (hi+lo, 2-term). USE_ALO=0: A hi only (1-term).
// CTA 128x128, KC=64, cp.async double buffer, 2 CTAs/SM.
// ------------------------------------------------------------------
#define TMM 128
#define TNN 128
#define KC 64
#define NCHUNK (DIM / KC)
#define LSTRIDE 144
#define TILE_B (128 * LSTRIDE)      // 18432
#define OFF_AHI 0
#define OFF_ALO (1 * TILE_B)
#define OFF_BHI (2 * TILE_B)
#define STAGE_B (3 * TILE_B)        // 55296
#define GEMM_SMEM (2 * STAGE_B)     // 110592

template <int USE_ALO>
__device__ __forceinline__ void load_chunk(
    uint32_t sbase, const __half* __restrict__ Ahi, const __half* __restrict__ Alo,
    const __half* __restrict__ Bhi, int row0, int col0, int k0, int tid)
{
    const int col16 = tid & 7;
    const int rb    = tid >> 3;
    const int kg    = k0 + col16 * 8;
#pragma unroll
    for (int t = 0; t < 4; ++t) {
        int r = rb + t * 32;
        uint32_t so = r * LSTRIDE + col16 * 16;
        size_t ga = (size_t)(row0 + r) * DIM + kg;
        size_t gb = (size_t)(col0 + r) * DIM + kg;
        CP_ASYNC16(sbase + OFF_AHI + so, Ahi + ga);
        if (USE_ALO) CP_ASYNC16(sbase + OFF_ALO + so, Alo + ga);
        CP_ASYNC16(sbase + OFF_BHI + so, Bhi + gb);
    }
}

// mode 0: fp32 [S][DIM]; mode 2: hi-only fp16 scatter [H][S][DK]
template <int USE_ALO>
__device__ __forceinline__ void gemm_tc_body(
    const __half* __restrict__ Ahi, const __half* __restrict__ Alo,
    const __half* __restrict__ Bhi,
    const float* __restrict__ bias, float bscale,
    float* __restrict__ outp, __half* __restrict__ ohi, int mode)
{
    extern __shared__ char smg[];
    const int tid  = threadIdx.x;
    const int wid  = tid >> 5;
    const int lane = tid & 31;
    const int row0 = blockIdx.y * TMM;
    const int col0 = blockIdx.x * TNN;
    const int wm   = (wid & 3) * 32;
    const int wn   = (wid >> 2) * 64;
    const uint32_t sb = smem_u32(smg);

    float c[2][8][4];
#pragma unroll
    for (int mt = 0; mt < 2; ++mt)
#pragma unroll
        for (int nt = 0; nt < 8; ++nt)
#pragma unroll
            for (int j = 0; j < 4; ++j) c[mt][nt][j] = 0.0f;

    const uint32_t a_off = (wm + (lane & 15)) * LSTRIDE + (lane >> 4) * 16;
    const uint32_t b_row = wn + (lane & 7) + ((lane >> 4) & 1) * 8;
    const uint32_t b_off = b_row * LSTRIDE + ((lane >> 3) & 1) * 16;

    load_chunk<USE_ALO>(sb, Ahi, Alo, Bhi, row0, col0, 0, tid);
    CP_COMMIT();

    for (int ch = 0; ch < NCHUNK; ++ch) {
        const uint32_t stage = sb + (ch & 1) * STAGE_B;
        if (ch + 1 < NCHUNK) {
            load_chunk<USE_ALO>(sb + ((ch + 1) & 1) * STAGE_B, Ahi, Alo, Bhi,
                                row0, col0, (ch + 1) * KC, tid);
            CP_COMMIT();
            CP_WAIT1();
        } else {
            CP_WAIT0();
        }
        __syncthreads();

#pragma unroll
        for (int ks = 0; ks < 4; ++ks) {
            const uint32_t kb = ks * 32;
            uint32_t ahi[2][4], alo[2][4];
#pragma unroll
            for (int mt = 0; mt < 2; ++mt) {
                uint32_t ad = stage + (uint32_t)(mt * 16 * LSTRIDE) + a_off + kb;
                LDSM_X4(ahi[mt][0], ahi[mt][1], ahi[mt][2], ahi[mt][3], ad + OFF_AHI);
                if (USE_ALO)
                    LDSM_X4(alo[mt][0], alo[mt][1], alo[mt][2], alo[mt][3], ad + OFF_ALO);
            }
            uint32_t bhi[8][2];
#pragma unroll
            for (int q = 0; q < 4; ++q) {
                uint32_t bd = stage + (uint32_t)(q * 16 * LSTRIDE) + b_off + kb;
                LDSM_X4(bhi[2 * q][0], bhi[2 * q][1], bhi[2 * q + 1][0], bhi[2 * q + 1][1],
                        bd + OFF_BHI);
            }
#pragma unroll
            for (int mt = 0; mt < 2; ++mt)
#pragma unroll
                for (int nt = 0; nt < 8; ++nt) {
                    MMA16816(c[mt][nt], ahi[mt], bhi[nt]);
                    if (USE_ALO) MMA16816(c[mt][nt], alo[mt], bhi[nt]);
                }
        }
        __syncthreads();
    }

#pragma unroll
    for (int mt = 0; mt < 2; ++mt) {
#pragma unroll
        for (int nt = 0; nt < 8; ++nt) {
            int cg = col0 + wn + nt * 8 + (lane & 3) * 2;
            float b0 = bias[cg] * bscale;
            float b1 = bias[cg + 1] * bscale;
            int r0 = row0 + wm + mt * 16 + (lane >> 2);
#pragma unroll
            for (int hh = 0; hh < 2; ++hh) {
                int r = r0 + hh * 8;
                float v0 = c[mt][nt][2 * hh + 0] + b0;
                float v1 = c[mt][nt][2 * hh + 1] + b1;
                if (mode == 0) {
                    float* ob = outp + (size_t)r * DIM + cg;
                    ob[0] = v0; ob[1] = v1;
                } else {
                    int hd = cg >> 7, d0 = cg & 127;
                    size_t base = ((size_t)hd * SEQ + r) * DK + d0;
                    *(__half2*)(ohi + base) =
                        __halves2half2(__float2half_rn(v0), __float2half_rn(v1));
                }
            }
        }
    }
}

__global__ __launch_bounds__(256, 2) void qkv_tc(
    const float* __restrict__ bq, const float* __restrict__ bk, const float* __restrict__ bvv)
{
    int z = blockIdx.z;
    const __half* W = g_wt + (size_t)z * DIM * DIM;
    if (z == 0) {
        // Q: exact A (2-term); scale folded into Wq + bias scale
        gemm_tc_body<1>(g_a_hi, g_a_lo, W, bq, 0.08838834764831845f, nullptr, g_q, 2);
    } else if (z == 1) {
        // K: 1-term (fp16-quantized downstream anyway)
        gemm_tc_body<0>(g_a_hi, g_a_lo, W, bk, 1.0f, nullptr, g_k, 2);
    } else {
        // V: 1-term
        gemm_tc_body<0>(g_a_hi, g_a_lo, W, bvv, 1.0f, nullptr, g_v, 2);
    }
}

__global__ __launch_bounds__(256, 2) void out_tc(const float* __restrict__ bo, float* __restrict__ out)
{
    gemm_tc_body<1>(g_a_hi, g_a_lo, g_wt + (size_t)3 * DIM * DIM, bo, 1.0f,
                    out, nullptr, 0);
}

// ------------------------------------------------------------------
// mma.sync fp16 causal flash attention
// Q, K, V fp16-quantized (1-term QK); P exact hi+lo (2-term PV).
// V row-major, transposed via ldmatrix.x4.trans.
// CTA: 128 q-rows x 1 head. 8 warps x 16 rows. KV tiles of 64.
// ------------------------------------------------------------------
#define QT 128
#define KT 64
#define QSTR 272                      // 256B payload + 16B pad
#define QB 0                          // Q: 128 rows x QSTR = 34816
#define QB_TOT (128 * QSTR)           // 34816
#define SK 0                          // K: 64 rows x QSTR = 17408
#define SV (64 * QSTR)                // V: 64 rows x QSTR = 17408
#define STAGE_SZ (2 * 64 * QSTR)      // 34816
#define ATTN_SMEM (QB_TOT + 2 * STAGE_SZ)   // 104448

__device__ __forceinline__ void attn_load_kv(uint32_t st, int h, int kv0, int tid)
{
    const __half* kh = g_k + ((size_t)h * SEQ + kv0) * DK;
    const __half* vh = g_v + ((size_t)h * SEQ + kv0) * DK;
    int r = tid >> 2;
#pragma unroll
    for (int i = 0; i < 4; ++i) {
        int u = (tid & 3) * 4 + i;
        CP_ASYNC16(st + SK + r * QSTR + u * 16, kh + (size_t)r * DK + u * 8);
        CP_ASYNC16(st + SV + r * QSTR + u * 16, vh + (size_t)r * DK + u * 8);
    }
}

__global__ __launch_bounds__(256, 1) void attn_mma()
{
    extern __shared__ char sma[];
    const uint32_t sb = smem_u32(sma);
    const int tid  = threadIdx.x;
    const int wid  = tid >> 5;
    const int lane = tid & 31;
    const int h    = blockIdx.y;
    const int qi   = 15 - blockIdx.x;      // heavy tiles first
    const int q0   = qi * QT;
    const int ntiles = 2 * (qi + 1);

    // prologue: Q tile (hi only) + stage 0 KV
    {
        const __half* qh = g_q + ((size_t)h * SEQ + q0) * DK;
        int r = tid >> 1;
#pragma unroll
        for (int i = 0; i < 8; ++i) {
            int u = (tid & 1) * 8 + i;
            CP_ASYNC16(sb + QB + r * QSTR + u * 16, qh + (size_t)r * DK + u * 8);
        }
        attn_load_kv(sb + QB_TOT, h, 0, tid);
        CP_COMMIT();
    }

    // per-lane fragment address components
    const uint32_t a_off  = (wid * 16 + (lane & 15)) * QSTR + (lane >> 4) * 16;
    const uint32_t bk_off = ((lane & 7) + ((lane >> 4) & 1) * 8) * QSTR + ((lane >> 3) & 1) * 16;
    // V via ldmatrix.trans: tiles (k0-7,d0)(k8-15,d0)(k0-7,d1)(k8-15,d1)
    const uint32_t bv_off = ((lane & 7) + ((lane >> 3) & 1) * 8) * QSTR + ((lane >> 4) & 1) * 16;

    const int row0_abs = q0 + wid * 16 + (lane >> 2);
    const int rowmax   = q0 + wid * 16 + 15;

    float o[16][4];
#pragma unroll
    for (int nt = 0; nt < 16; ++nt)
#pragma unroll
        for (int j = 0; j < 4; ++j) o[nt][j] = 0.0f;
    float m0 = -1e4f, m1 = -1e4f, l0 = 0.0f, l1 = 0.0f;

    for (int jt = 0; jt < ntiles; ++jt) {
        if (jt + 1 < ntiles) {
            attn_load_kv(sb + QB_TOT + ((jt + 1) & 1) * STAGE_SZ, h, (jt + 1) * KT, tid);
            CP_COMMIT();
            CP_WAIT1();
        } else {
            CP_WAIT0();
        }
        __syncthreads();

        const int kv0 = jt * KT;
        if (kv0 <= rowmax) {
            const uint32_t st = sb + QB_TOT + (jt & 1) * STAGE_SZ;

            // ---- S = Q K^T (1-term fp16) ----
            float s[8][4];
#pragma unroll
            for (int nt = 0; nt < 8; ++nt)
#pragma unroll
                for (int j = 0; j < 4; ++j) s[nt][j] = 0.0f;

#pragma unroll
            for (int ks = 0; ks < 8; ++ks) {
                uint32_t ah[4];
                LDSM_X4(ah[0], ah[1], ah[2], ah[3], sb + QB + a_off + ks * 32);
                uint32_t bh[8][2];
#pragma unroll
                for (int q = 0; q < 4; ++q) {
                    uint32_t ba = st + SK + bk_off + q * (16 * QSTR) + ks * 32;
                    LDSM_X4(bh[2 * q][0], bh[2 * q][1], bh[2 * q + 1][0], bh[2 * q + 1][1], ba);
                }
#pragma unroll
                for (int nt = 0; nt < 8; ++nt) MMA16816(s[nt], ah, bh[nt]);
            }

            // ---- causal mask ----
            if (kv0 + KT - 1 > q0 + wid * 16) {
#pragma unroll
                for (int nt = 0; nt < 8; ++nt) {
                    int cb = kv0 + nt * 8 + (lane & 3) * 2;
#pragma unroll
                    for (int j = 0; j < 4; ++j) {
                        int col = cb + (j & 1);
                        int row = row0_abs + (j >> 1) * 8;
                        if (col > row) s[nt][j] = -1e30f;
                    }
                }
            }

            // ---- online softmax ----
            float tm0 = -1e30f, tm1 = -1e30f;
#pragma unroll
            for (int nt = 0; nt < 8; ++nt) {
                tm0 = fmaxf(tm0, fmaxf(s[nt][0], s[nt][1]));
                tm1 = fmaxf(tm1, fmaxf(s[nt][2], s[nt][3]));
            }
            tm0 = fmaxf(tm0, __shfl_xor_sync(0xffffffffu, tm0, 1));
            tm0 = fmaxf(tm0, __shfl_xor_sync(0xffffffffu, tm0, 2));
            tm1 = fmaxf(tm1, __shfl_xor_sync(0xffffffffu, tm1, 1));
            tm1 = fmaxf(tm1, __shfl_xor_sync(0xffffffffu, tm1, 2));
            float mn0 = fmaxf(fmaxf(m0, tm0), -1e4f);
            float mn1 = fmaxf(fmaxf(m1, tm1), -1e4f);
            float al0 = __expf(m0 - mn0), al1 = __expf(m1 - mn1);
            m0 = mn0; m1 = mn1;
            float ls0 = 0.0f, ls1 = 0.0f;
#pragma unroll
            for (int nt = 0; nt < 8; ++nt) {
                s[nt][0] = __expf(s[nt][0] - mn0);
                s[nt][1] = __expf(s[nt][1] - mn0);
                s[nt][2] = __expf(s[nt][2] - mn1);
                s[nt][3] = __expf(s[nt][3] - mn1);
                ls0 += s[nt][0] + s[nt][1];
                ls1 += s[nt][2] + s[nt][3];
            }
            l0 = l0 * al0 + ls0;
            l1 = l1 * al1 + ls1;
#pragma unroll
            for (int nt = 0; nt < 16; ++nt) {
                o[nt][0] *= al0; o[nt][1] *= al0;
                o[nt][2] *= al1; o[nt][3] *= al1;
            }

            // ---- pack P into PV A-frags (exact hi+lo) ----
            uint32_t aph[4][4], apl[4][4];
#pragma unroll
            for (int pr = 0; pr < 4; ++pr) {
#pragma unroll
                for (int half = 0; half < 2; ++half) {
                    int nt = 2 * pr + half;
                    __half h0 = __float2half_rn(s[nt][0]);
                    __half h1 = __float2half_rn(s[nt][1]);
                    __half h2 = __float2half_rn(s[nt][2]);
                    __half h3 = __float2half_rn(s[nt][3]);
                    __half e0 = __float2half_rn(s[nt][0] - __half2float(h0));
                    __half e1 = __float2half_rn(s[nt][1] - __half2float(h1));
                    __half e2 = __float2half_rn(s[nt][2] - __half2float(h2));
                    __half e3 = __float2half_rn(s[nt][3] - __half2float(h3));
                    aph[pr][2 * half + 0] = h2u(__halves2half2(h0, h1));
                    aph[pr][2 * half + 1] = h2u(__halves2half2(h2, h3));
                    apl[pr][2 * half + 0] = h2u(__halves2half2(e0, e1));
                    apl[pr][2 * half + 1] = h2u(__halves2half2(e2, e3));
                }
            }

            // ---- O += P V (ph·vh + pl·vh), V frags via ldmatrix.trans ----
#pragma unroll
            for (int kp = 0; kp < 4; ++kp) {
#pragma unroll
                for (int p = 0; p < 8; ++p) {
                    uint32_t r0, r1, r2, r3;
                    LDSM_X4_T(r0, r1, r2, r3,
                              st + SV + bv_off + kp * (16 * QSTR) + p * 32);
                    uint32_t b01[2] = {r0, r1};
                    uint32_t b23[2] = {r2, r3};
                    MMA16816(o[2 * p + 0], aph[kp], b01);
                    MMA16816(o[2 * p + 0], apl[kp], b01);
                    MMA16816(o[2 * p + 1], aph[kp], b23);
                    MMA16816(o[2 * p + 1], apl[kp], b23);
                }
            }
        }
        __syncthreads();
    }

    // ---- epilogue: normalize, exact split, write att into A operand ----
    l0 += __shfl_xor_sync(0xffffffffu, l0, 1);
    l0 += __shfl_xor_sync(0xffffffffu, l0, 2);
    l1 += __shfl_xor_sync(0xffffffffu, l1, 1);
    l1 += __shfl_xor_sync(0xffffffffu, l1, 2);
    float inv0 = 1.0f / l0, inv1 = 1.0f / l1;

    const int r0 = row0_abs;
    const int r1 = row0_abs + 8;
#pragma unroll
    for (int nt = 0; nt < 16; ++nt) {
        int d = h * DK + nt * 8 + (lane & 3) * 2;
        float v00 = o[nt][0] * inv0, v01 = o[nt][1] * inv0;
        float v10 = o[nt][2] * inv1, v11 = o[nt][3] * inv1;
        __half h00 = __float2half_rn(v00), h01 = __float2half_rn(v01);
        __half h10 = __float2half_rn(v10), h11 = __float2half_rn(v11);
        *(__half2*)(g_a_hi + (size_t)r0 * DIM + d) = __halves2half2(h00, h01);
        *(__half2*)(g_a_lo + (size_t)r0 * DIM + d) =
            __halves2half2(__float2half_rn(v00 - __half2float(h00)),
                           __float2half_rn(v01 - __half2float(h01)));
        *(__half2*)(g_a_hi + (size_t)r1 * DIM + d) = __halves2half2(h10, h11);
        *(__half2*)(g_a_lo + (size_t)r1 * DIM + d) =
            __halves2half2(__float2half_rn(v10 - __half2float(h10)),
                           __float2half_rn(v11 - __half2float(h11)));
    }
}

// ------------------------------------------------------------------
// Launch
// ------------------------------------------------------------------
extern "C" void kernel_launch(void* const* d_in, const int* in_sizes, int n_in,
                              void* d_out, int out_size)
{
    const float* x  = (const float*)d_in[0];
    const float* Wq = (const float*)d_in[1];
    const float* bq = (const float*)d_in[2];
    const float* Wk = (const float*)d_in[3];
    const float* bk = (const float*)d_in[4];
    const float* Wv = (const float*)d_in[5];
    const float* bv = (const float*)d_in[6];
    const float* Wo = (const float*)d_in[7];
    const float* bo = (const float*)d_in[8];
    float* out = (float*)d_out;

    __half *a_hi, *a_lo;
    cudaGetSymbolAddress((void**)&a_hi, g_a_hi);
    cudaGetSymbolAddress((void**)&a_lo, g_a_lo);

    cudaFuncSetAttribute(qkv_tc, cudaFuncAttributeMaxDynamicSharedMemorySize, GEMM_SMEM);
    cudaFuncSetAttribute(out_tc, cudaFuncAttributeMaxDynamicSharedMemorySize, GEMM_SMEM);
    cudaFuncSetAttribute(attn_mma, cudaFuncAttributeMaxDynamicSharedMemorySize, ATTN_SMEM);

    dim3 tblk(32, 8);

    // 1) operand conversions
    convert_split<<<SEQ * DIM / 1024, 256>>>(x, a_hi, a_lo);
    convert_w_all<<<dim3(DIM / 32, DIM / 32, 4), tblk>>>(Wq, Wk, Wv, Wo);

    // 2) Q/K/V projections (Q 2-term; K,V 1-term)
    qkv_tc<<<dim3(DIM / TNN, SEQ / TMM, 3), 256, GEMM_SMEM>>>(bq, bk, bv);

    // 3) tensor-core causal flash attention (1-term QK, 2-term PV)
    attn_mma<<<dim3(SEQ / QT, NH), 256, ATTN_SMEM>>>();

    // 4) output projection (2-term)
    out_tc<<<dim3(DIM / TNN, SEQ / TMM), 256, GEMM_SMEM>>>(bo, out);
}